// round 1
// baseline (speedup 1.0000x reference)
#include <cuda_runtime.h>
#include <math.h>

#define D_MODEL 1024
#define NHEAD   16
#define DK      64
#define DFF     4096
#define BATCH   2
#define SEQ     2048
#define MTOT    (BATCH*SEQ)   /* 4096 */
#define EPS_RMS 1e-5f

// ---------------- scratch (no allocations allowed) ----------------
__device__ float g_xn [MTOT*D_MODEL];
__device__ float g_q  [MTOT*D_MODEL];
__device__ float g_k  [MTOT*D_MODEL];
__device__ float g_v  [MTOT*D_MODEL];
__device__ float g_att[MTOT*D_MODEL];
__device__ float g_x1 [MTOT*D_MODEL];
__device__ float g_ffh[MTOT*DFF];

// ---------------- RMSNorm ----------------
// one block per row, 256 threads, D=1024 -> one float4 per thread
__global__ void __launch_bounds__(256) rmsnorm_kernel(
    const float* __restrict__ x, const float* __restrict__ g, float* __restrict__ y)
{
    const int row = blockIdx.x;
    const float4* x4 = (const float4*)(x + (size_t)row * D_MODEL);
    const float4* g4 = (const float4*)g;

    float4 v = x4[threadIdx.x];
    float s = v.x*v.x + v.y*v.y + v.z*v.z + v.w*v.w;

    #pragma unroll
    for (int m = 16; m; m >>= 1) s += __shfl_xor_sync(0xffffffffu, s, m);

    __shared__ float red[8];
    int warp = threadIdx.x >> 5, lane = threadIdx.x & 31;
    if (lane == 0) red[warp] = s;
    __syncthreads();
    if (warp == 0) {
        float t = (lane < 8) ? red[lane] : 0.f;
        t += __shfl_xor_sync(0xffffffffu, t, 4);
        t += __shfl_xor_sync(0xffffffffu, t, 2);
        t += __shfl_xor_sync(0xffffffffu, t, 1);
        if (lane == 0) red[0] = t;
    }
    __syncthreads();

    float rms = rsqrtf(red[0] * (1.0f / D_MODEL) + EPS_RMS);
    float4 gg = g4[threadIdx.x];
    float4 o;
    o.x = v.x * rms * gg.x;
    o.y = v.y * rms * gg.y;
    o.z = v.z * rms * gg.z;
    o.w = v.w * rms * gg.w;
    ((float4*)(y + (size_t)row * D_MODEL))[threadIdx.x] = o;
}

// ---------------- GELU (exact erf) ----------------
__device__ __forceinline__ float gelu_f(float v) {
    return 0.5f * v * (1.0f + erff(v * 0.70710678118654752f));
}

// ---------------- SGEMM: C[M,N] = A[M,K] * B[N,K]^T  (torch Linear) ----------------
// 128x128x16 tile, 256 threads, 8x8 per thread, transposed smem tiles.
// EPI: 0 = none, 1 = add residual R, 2 = gelu
template <int EPI>
__global__ void __launch_bounds__(256) sgemm_nt(
    const float* __restrict__ A, const float* __restrict__ B,
    const float* __restrict__ R, float* __restrict__ C,
    int M, int N, int K)
{
    __shared__ float As[16][128];
    __shared__ float Bs[16][128];

    const int tid = threadIdx.x;
    const int tx = tid & 15;
    const int ty = tid >> 4;
    const int bm = blockIdx.y * 128;
    const int bn = blockIdx.x * 128;

    const int lrow = tid >> 2;        // 0..63
    const int lk4  = (tid & 3) * 4;   // 0,4,8,12

    float acc[8][8];
    #pragma unroll
    for (int i = 0; i < 8; i++)
        #pragma unroll
        for (int j = 0; j < 8; j++) acc[i][j] = 0.f;

    const float* Ag = A + (size_t)(bm + lrow) * K + lk4;
    const float* Bg = B + (size_t)(bn + lrow) * K + lk4;

    for (int k0 = 0; k0 < K; k0 += 16) {
        #pragma unroll
        for (int r = 0; r < 2; r++) {
            float4 av = *(const float4*)(Ag + (size_t)r * 64 * K + k0);
            float4 bv = *(const float4*)(Bg + (size_t)r * 64 * K + k0);
            int row = lrow + r * 64;
            As[lk4 + 0][row] = av.x; As[lk4 + 1][row] = av.y;
            As[lk4 + 2][row] = av.z; As[lk4 + 3][row] = av.w;
            Bs[lk4 + 0][row] = bv.x; Bs[lk4 + 1][row] = bv.y;
            Bs[lk4 + 2][row] = bv.z; Bs[lk4 + 3][row] = bv.w;
        }
        __syncthreads();

        #pragma unroll
        for (int kk = 0; kk < 16; kk++) {
            float a[8], b[8];
            *(float4*)&a[0] = *(const float4*)&As[kk][ty * 8];
            *(float4*)&a[4] = *(const float4*)&As[kk][ty * 8 + 4];
            *(float4*)&b[0] = *(const float4*)&Bs[kk][tx * 8];
            *(float4*)&b[4] = *(const float4*)&Bs[kk][tx * 8 + 4];
            #pragma unroll
            for (int i = 0; i < 8; i++)
                #pragma unroll
                for (int j = 0; j < 8; j++)
                    acc[i][j] = fmaf(a[i], b[j], acc[i][j]);
        }
        __syncthreads();
    }

    #pragma unroll
    for (int i = 0; i < 8; i++) {
        int row = bm + ty * 8 + i;
        float* Cr = C + (size_t)row * N + bn + tx * 8;
        const float* Rr = R + (size_t)row * N + bn + tx * 8;  // only used if EPI==1
        #pragma unroll
        for (int j = 0; j < 8; j += 4) {
            float v0 = acc[i][j + 0], v1 = acc[i][j + 1];
            float v2 = acc[i][j + 2], v3 = acc[i][j + 3];
            if (EPI == 1) {
                float4 rr = *(const float4*)(Rr + j);
                v0 += rr.x; v1 += rr.y; v2 += rr.z; v3 += rr.w;
            } else if (EPI == 2) {
                v0 = gelu_f(v0); v1 = gelu_f(v1);
                v2 = gelu_f(v2); v3 = gelu_f(v3);
            }
            float4 o = make_float4(v0, v1, v2, v3);
            *(float4*)(Cr + j) = o;
        }
    }
}

// ---------------- causal flash attention (fp32) ----------------
// grid: (32 q-tiles, 32 batch*head), 256 threads, 64q x 64k tiles, d_k = 64.
#define BQ  64
#define BKV 64
#define FPAD 65

__global__ void __launch_bounds__(256) flash_attn(
    const float* __restrict__ Q, const float* __restrict__ Kg,
    const float* __restrict__ V, float* __restrict__ O)
{
    extern __shared__ float sm[];
    float* Qs = sm;                 // [64][65]
    float* Ks = Qs + 64 * FPAD;
    float* Vs = Ks + 64 * FPAD;
    float* Ps = Vs + 64 * FPAD;

    const int tid = threadIdx.x;
    const int tx = tid & 15;
    const int ty = tid >> 4;
    const int qi = blockIdx.x;          // 0..31
    const int bh = blockIdx.y;          // 0..31
    const int b  = bh >> 4;
    const int h  = bh & 15;
    const size_t qrow0 = (size_t)(b * SEQ + qi * BQ);
    const int fo = h * DK;
    const float scale = 0.125f;         // 1/sqrt(64)

    // load Q tile: 4096 floats = 1024 float4, 4 per thread
    #pragma unroll
    for (int it = 0; it < 4; it++) {
        int idx = tid + it * 256;
        int r  = idx >> 4;
        int c4 = (idx & 15) << 2;
        float4 qv = *(const float4*)(Q + (qrow0 + r) * D_MODEL + fo + c4);
        Qs[r * FPAD + c4 + 0] = qv.x; Qs[r * FPAD + c4 + 1] = qv.y;
        Qs[r * FPAD + c4 + 2] = qv.z; Qs[r * FPAD + c4 + 3] = qv.w;
    }

    float m_i[4], l_i[4], acc[4][4];
    #pragma unroll
    for (int i = 0; i < 4; i++) {
        m_i[i] = -1e30f; l_i[i] = 0.f;
        #pragma unroll
        for (int j = 0; j < 4; j++) acc[i][j] = 0.f;
    }

    for (int kt = 0; kt <= qi; kt++) {
        // load K,V tiles
        #pragma unroll
        for (int it = 0; it < 4; it++) {
            int idx = tid + it * 256;
            int r  = idx >> 4;
            int c4 = (idx & 15) << 2;
            size_t grow = (size_t)(b * SEQ + kt * BKV + r) * D_MODEL + fo + c4;
            float4 kv = *(const float4*)(Kg + grow);
            float4 vv = *(const float4*)(V  + grow);
            Ks[r * FPAD + c4 + 0] = kv.x; Ks[r * FPAD + c4 + 1] = kv.y;
            Ks[r * FPAD + c4 + 2] = kv.z; Ks[r * FPAD + c4 + 3] = kv.w;
            Vs[r * FPAD + c4 + 0] = vv.x; Vs[r * FPAD + c4 + 1] = vv.y;
            Vs[r * FPAD + c4 + 2] = vv.z; Vs[r * FPAD + c4 + 3] = vv.w;
        }
        __syncthreads();

        // S = Q K^T
        float s[4][4];
        #pragma unroll
        for (int i = 0; i < 4; i++)
            #pragma unroll
            for (int j = 0; j < 4; j++) s[i][j] = 0.f;

        #pragma unroll 4
        for (int d = 0; d < 64; d++) {
            float a0 = Qs[(ty * 4 + 0) * FPAD + d];
            float a1 = Qs[(ty * 4 + 1) * FPAD + d];
            float a2 = Qs[(ty * 4 + 2) * FPAD + d];
            float a3 = Qs[(ty * 4 + 3) * FPAD + d];
            float b0 = Ks[(tx * 4 + 0) * FPAD + d];
            float b1 = Ks[(tx * 4 + 1) * FPAD + d];
            float b2 = Ks[(tx * 4 + 2) * FPAD + d];
            float b3 = Ks[(tx * 4 + 3) * FPAD + d];
            s[0][0] = fmaf(a0, b0, s[0][0]); s[0][1] = fmaf(a0, b1, s[0][1]);
            s[0][2] = fmaf(a0, b2, s[0][2]); s[0][3] = fmaf(a0, b3, s[0][3]);
            s[1][0] = fmaf(a1, b0, s[1][0]); s[1][1] = fmaf(a1, b1, s[1][1]);
            s[1][2] = fmaf(a1, b2, s[1][2]); s[1][3] = fmaf(a1, b3, s[1][3]);
            s[2][0] = fmaf(a2, b0, s[2][0]); s[2][1] = fmaf(a2, b1, s[2][1]);
            s[2][2] = fmaf(a2, b2, s[2][2]); s[2][3] = fmaf(a2, b3, s[2][3]);
            s[3][0] = fmaf(a3, b0, s[3][0]); s[3][1] = fmaf(a3, b1, s[3][1]);
            s[3][2] = fmaf(a3, b2, s[3][2]); s[3][3] = fmaf(a3, b3, s[3][3]);
        }

        // scale + causal mask (only diagonal tile is partial)
        #pragma unroll
        for (int i = 0; i < 4; i++)
            #pragma unroll
            for (int j = 0; j < 4; j++) {
                s[i][j] *= scale;
                if (kt == qi && (tx * 4 + j) > (ty * 4 + i)) s[i][j] = -1e30f;
            }

        // online softmax
        #pragma unroll
        for (int i = 0; i < 4; i++) {
            float mloc = fmaxf(fmaxf(s[i][0], s[i][1]), fmaxf(s[i][2], s[i][3]));
            mloc = fmaxf(mloc, __shfl_xor_sync(0xffffffffu, mloc, 8));
            mloc = fmaxf(mloc, __shfl_xor_sync(0xffffffffu, mloc, 4));
            mloc = fmaxf(mloc, __shfl_xor_sync(0xffffffffu, mloc, 2));
            mloc = fmaxf(mloc, __shfl_xor_sync(0xffffffffu, mloc, 1));
            float mnew = fmaxf(m_i[i], mloc);
            float alpha = __expf(m_i[i] - mnew);
            float psum = 0.f;
            #pragma unroll
            for (int j = 0; j < 4; j++) {
                s[i][j] = __expf(s[i][j] - mnew);
                psum += s[i][j];
            }
            psum += __shfl_xor_sync(0xffffffffu, psum, 8);
            psum += __shfl_xor_sync(0xffffffffu, psum, 4);
            psum += __shfl_xor_sync(0xffffffffu, psum, 2);
            psum += __shfl_xor_sync(0xffffffffu, psum, 1);
            l_i[i] = l_i[i] * alpha + psum;
            m_i[i] = mnew;
            #pragma unroll
            for (int j = 0; j < 4; j++) acc[i][j] *= alpha;
            // stage P
            #pragma unroll
            for (int j = 0; j < 4; j++)
                Ps[(ty * 4 + i) * FPAD + tx * 4 + j] = s[i][j];
        }
        __syncthreads();

        // O += P V
        #pragma unroll 4
        for (int c = 0; c < 64; c++) {
            float v0 = Vs[c * FPAD + tx * 4 + 0];
            float v1 = Vs[c * FPAD + tx * 4 + 1];
            float v2 = Vs[c * FPAD + tx * 4 + 2];
            float v3 = Vs[c * FPAD + tx * 4 + 3];
            #pragma unroll
            for (int i = 0; i < 4; i++) {
                float p = Ps[(ty * 4 + i) * FPAD + c];
                acc[i][0] = fmaf(p, v0, acc[i][0]);
                acc[i][1] = fmaf(p, v1, acc[i][1]);
                acc[i][2] = fmaf(p, v2, acc[i][2]);
                acc[i][3] = fmaf(p, v3, acc[i][3]);
            }
        }
        __syncthreads();
    }

    // write out
    #pragma unroll
    for (int i = 0; i < 4; i++) {
        float invl = 1.f / l_i[i];
        float4 o = make_float4(acc[i][0] * invl, acc[i][1] * invl,
                               acc[i][2] * invl, acc[i][3] * invl);
        *(float4*)(O + (qrow0 + ty * 4 + i) * D_MODEL + fo + tx * 4) = o;
    }
}

// ---------------- host ----------------
extern "C" void kernel_launch(void* const* d_in, const int* in_sizes, int n_in,
                              void* d_out, int out_size)
{
    const float* x  = (const float*)d_in[0];
    const float* wq = (const float*)d_in[1];
    const float* wk = (const float*)d_in[2];
    const float* wv = (const float*)d_in[3];
    const float* wo = (const float*)d_in[4];
    const float* w1 = (const float*)d_in[5];
    const float* w2 = (const float*)d_in[6];
    const float* g1 = (const float*)d_in[7];
    const float* g2 = (const float*)d_in[8];
    float* out = (float*)d_out;

    float *xn, *q, *k, *v, *att, *x1, *ffh;
    cudaGetSymbolAddress((void**)&xn,  g_xn);
    cudaGetSymbolAddress((void**)&q,   g_q);
    cudaGetSymbolAddress((void**)&k,   g_k);
    cudaGetSymbolAddress((void**)&v,   g_v);
    cudaGetSymbolAddress((void**)&att, g_att);
    cudaGetSymbolAddress((void**)&x1,  g_x1);
    cudaGetSymbolAddress((void**)&ffh, g_ffh);

    const int flash_smem = 4 * 64 * FPAD * (int)sizeof(float);   // 66560 B
    cudaFuncSetAttribute(flash_attn, cudaFuncAttributeMaxDynamicSharedMemorySize, flash_smem);

    // 1. xn = rmsnorm(x, g1)
    rmsnorm_kernel<<<MTOT, 256>>>(x, g1, xn);

    // 2-4. q,k,v = xn @ W^T
    dim3 gproj(D_MODEL / 128, MTOT / 128);
    sgemm_nt<0><<<gproj, 256>>>(xn, wq, nullptr, q, MTOT, D_MODEL, D_MODEL);
    sgemm_nt<0><<<gproj, 256>>>(xn, wk, nullptr, k, MTOT, D_MODEL, D_MODEL);
    sgemm_nt<0><<<gproj, 256>>>(xn, wv, nullptr, v, MTOT, D_MODEL, D_MODEL);

    // 5. att = causal_attention(q,k,v)
    flash_attn<<<dim3(SEQ / BQ, BATCH * NHEAD), 256, flash_smem>>>(q, k, v, att);

    // 6. x1 = x + att @ wo^T
    sgemm_nt<1><<<gproj, 256>>>(att, wo, x, x1, MTOT, D_MODEL, D_MODEL);

    // 7. xn = rmsnorm(x1, g2)
    rmsnorm_kernel<<<MTOT, 256>>>(x1, g2, xn);

    // 8. ffh = gelu(xn @ w1^T)
    dim3 gff1(DFF / 128, MTOT / 128);
    sgemm_nt<2><<<gff1, 256>>>(xn, w1, nullptr, ffh, MTOT, DFF, D_MODEL);

    // 9. out = x1 + ffh @ w2^T
    sgemm_nt<1><<<gproj, 256>>>(ffh, w2, x1, out, MTOT, D_MODEL, DFF);
}

// round 5
// speedup vs baseline: 2.7971x; 2.7971x over previous
#include <cuda_runtime.h>
#include <cuda_fp16.h>
#include <math.h>
#include <stdint.h>

#define D_MODEL 1024
#define NHEAD   16
#define DK      64
#define DFF     4096
#define BATCH   2
#define SEQ     2048
#define MTOT    (BATCH*SEQ)   /* 4096 */
#define EPS_RMS 1e-5f

// ================= low-level helpers (baseline PTX ISA, no 'a' features) ===
__device__ __forceinline__ uint32_t smem_to_u32(const void* p) {
    uint32_t a;
    asm("{ .reg .u64 t; cvta.to.shared.u64 t, %1; cvt.u32.u64 %0, t; }" : "=r"(a) : "l"(p));
    return a;
}
__device__ __forceinline__ void cp_async16(uint32_t dst, const void* src) {
    asm volatile("cp.async.cg.shared.global [%0], [%1], 16;" :: "r"(dst), "l"(src));
}
#define CP_COMMIT() asm volatile("cp.async.commit_group;" ::: "memory")
#define CP_WAIT(n)  asm volatile("cp.async.wait_group %0;" :: "n"(n) : "memory")

__device__ __forceinline__ void ldsm_x4(uint32_t& r0, uint32_t& r1, uint32_t& r2, uint32_t& r3,
                                        uint32_t addr) {
    asm volatile("ldmatrix.sync.aligned.m8n8.x4.shared.b16 {%0,%1,%2,%3}, [%4];"
        : "=r"(r0), "=r"(r1), "=r"(r2), "=r"(r3) : "r"(addr));
}
__device__ __forceinline__ void mma16816(float* c, const uint32_t* a, uint32_t b0, uint32_t b1) {
    asm volatile("mma.sync.aligned.m16n8k16.row.col.f32.f16.f16.f32 "
        "{%0,%1,%2,%3}, {%4,%5,%6,%7}, {%8,%9}, {%0,%1,%2,%3};"
        : "+f"(c[0]), "+f"(c[1]), "+f"(c[2]), "+f"(c[3])
        : "r"(a[0]), "r"(a[1]), "r"(a[2]), "r"(a[3]), "r"(b0), "r"(b1));
}

// ================= scratch buffers =================
__device__ __half g_xnh [MTOT*D_MODEL];
__device__ float  g_q   [MTOT*D_MODEL];
__device__ float  g_k   [MTOT*D_MODEL];
__device__ float  g_v   [MTOT*D_MODEL];
__device__ __half g_atth[MTOT*D_MODEL];
__device__ float  g_x1  [MTOT*D_MODEL];
__device__ __half g_ffhh[MTOT*DFF];
__device__ __half g_wqh [D_MODEL*D_MODEL];
__device__ __half g_wkh [D_MODEL*D_MODEL];
__device__ __half g_wvh [D_MODEL*D_MODEL];
__device__ __half g_woh [D_MODEL*D_MODEL];
__device__ __half g_w1h [DFF*D_MODEL];
__device__ __half g_w2h [D_MODEL*DFF];

// ================= fp32 -> fp16 convert =================
__global__ void __launch_bounds__(256) f2h_kernel(
    const float* __restrict__ a, __half* __restrict__ b, int n)
{
    int i = (blockIdx.x * 256 + threadIdx.x) * 4;
    if (i < n) {
        float4 v = *(const float4*)(a + i);
        __half2 h0 = __floats2half2_rn(v.x, v.y);
        __half2 h1 = __floats2half2_rn(v.z, v.w);
        ((__half2*)(b + i))[0] = h0;
        ((__half2*)(b + i))[1] = h1;
    }
}

// ================= RMSNorm -> fp16 =================
__global__ void __launch_bounds__(256) rmsnorm_h_kernel(
    const float* __restrict__ x, const float* __restrict__ g, __half* __restrict__ y)
{
    const int row = blockIdx.x;
    const float4* x4 = (const float4*)(x + (size_t)row * D_MODEL);
    const float4* g4 = (const float4*)g;

    float4 v = x4[threadIdx.x];
    float s = v.x*v.x + v.y*v.y + v.z*v.z + v.w*v.w;

    #pragma unroll
    for (int m = 16; m; m >>= 1) s += __shfl_xor_sync(0xffffffffu, s, m);

    __shared__ float red[8];
    int warp = threadIdx.x >> 5, lane = threadIdx.x & 31;
    if (lane == 0) red[warp] = s;
    __syncthreads();
    if (warp == 0) {
        float t = (lane < 8) ? red[lane] : 0.f;
        t += __shfl_xor_sync(0xffffffffu, t, 4);
        t += __shfl_xor_sync(0xffffffffu, t, 2);
        t += __shfl_xor_sync(0xffffffffu, t, 1);
        if (lane == 0) red[0] = t;
    }
    __syncthreads();

    float rms = rsqrtf(red[0] * (1.0f / D_MODEL) + EPS_RMS);
    float4 gg = g4[threadIdx.x];
    __half2 h0 = __floats2half2_rn(v.x * rms * gg.x, v.y * rms * gg.y);
    __half2 h1 = __floats2half2_rn(v.z * rms * gg.z, v.w * rms * gg.w);
    __half2* yo = (__half2*)(y + (size_t)row * D_MODEL + threadIdx.x * 4);
    yo[0] = h0; yo[1] = h1;
}

// ================= GELU =================
__device__ __forceinline__ float gelu_f(float v) {
    return 0.5f * v * (1.0f + erff(v * 0.70710678118654752f));
}

// ====== HGEMM via mma.sync: C[M,N] = A[M,K] * B[N,K]^T (torch Linear NT) ======
// 128x128 CTA tile, 8 warps (2 x 4), warp tile 64x32, K-chunk 32, cp.async
// double buffering. Smem rows padded to 40 halves (80 B).
// EPI: 0 = fp32 out; 1 = fp32 out + residual; 2 = fp16 out with GELU
#define KCH   32
#define SPAD  40

__device__ __forceinline__ void load_chunk_ca(
    const __half* __restrict__ G, int base_row, int K, int k0, int tid, uint32_t s_stage)
{
    #pragma unroll
    for (int i = 0; i < 2; i++) {
        int idx = tid + i * 256;      // 0..511
        int row = idx >> 2;           // 0..127
        int seg = idx & 3;            // 16B segment (8 halves)
        const __half* src = G + (size_t)(base_row + row) * K + k0 + seg * 8;
        uint32_t dst = s_stage + (uint32_t)(row * SPAD + seg * 8) * 2;
        cp_async16(dst, src);
    }
}

template <int EPI>
__global__ void __launch_bounds__(256) hgemm_mma(
    const __half* __restrict__ A, const __half* __restrict__ B,
    const float* __restrict__ R, float* __restrict__ Cf, __half* __restrict__ Ch,
    int M, int N, int K)
{
    __shared__ __half As[2][128][SPAD];
    __shared__ __half Bs[2][128][SPAD];

    const int tid = threadIdx.x;
    const int lane = tid & 31;
    const int wid = tid >> 5;
    const int wy = wid & 1;        // 0..1 -> M offset 64*wy
    const int wx = wid >> 1;       // 0..3 -> N offset 32*wx
    const int bm = blockIdx.y * 128;
    const int bn = blockIdx.x * 128;

    const uint32_t a_base = smem_to_u32(&As[0][0][0]);
    const uint32_t b_base = smem_to_u32(&Bs[0][0][0]);
    const uint32_t stage_bytes = 128 * SPAD * 2;

    // ldmatrix source rows/cols for this lane
    const int lrow = lane & 15;
    const int koff = (lane >> 4) * 8;

    float acc[4][4][4];
    #pragma unroll
    for (int i = 0; i < 4; i++)
        #pragma unroll
        for (int j = 0; j < 4; j++)
            #pragma unroll
            for (int r = 0; r < 4; r++) acc[i][j][r] = 0.f;

    const int nch = K / KCH;

    // prologue: chunk 0 -> stage 0
    load_chunk_ca(A, bm, K, 0, tid, a_base);
    load_chunk_ca(B, bn, K, 0, tid, b_base);
    CP_COMMIT();

    for (int c = 0; c < nch; ++c) {
        const int st = c & 1;
        if (c + 1 < nch) {
            const uint32_t off = (uint32_t)(st ^ 1) * stage_bytes;
            load_chunk_ca(A, bm, K, (c + 1) * KCH, tid, a_base + off);
            load_chunk_ca(B, bn, K, (c + 1) * KCH, tid, b_base + off);
            CP_COMMIT();
            CP_WAIT(1);
        } else {
            CP_WAIT(0);
        }
        __syncthreads();

        const uint32_t a_st = a_base + (uint32_t)st * stage_bytes;
        const uint32_t b_st = b_base + (uint32_t)st * stage_bytes;

        #pragma unroll
        for (int ks = 0; ks < 2; ++ks) {
            uint32_t af[4][4];
            #pragma unroll
            for (int ma = 0; ma < 4; ++ma) {
                uint32_t addr = a_st +
                    (uint32_t)((wy * 64 + ma * 16 + lrow) * SPAD + ks * 16 + koff) * 2;
                ldsm_x4(af[ma][0], af[ma][1], af[ma][2], af[ma][3], addr);
            }
            uint32_t bf[2][4];
            #pragma unroll
            for (int nb = 0; nb < 2; ++nb) {
                uint32_t addr = b_st +
                    (uint32_t)((wx * 32 + nb * 16 + lrow) * SPAD + ks * 16 + koff) * 2;
                ldsm_x4(bf[nb][0], bf[nb][1], bf[nb][2], bf[nb][3], addr);
            }
            // ldmatrix register map for B: [0]=(n0-7,k0-7) [1]=(n8-15,k0-7)
            //                              [2]=(n0-7,k8-15) [3]=(n8-15,k8-15)
            // mma needs b0 = k0-7 slice, b1 = k8-15 slice of the SAME n-block.
            #pragma unroll
            for (int ma = 0; ma < 4; ++ma) {
                #pragma unroll
                for (int na = 0; na < 4; ++na) {
                    const uint32_t b0 = bf[na >> 1][(na & 1)];
                    const uint32_t b1 = bf[na >> 1][(na & 1) + 2];
                    mma16816(acc[ma][na], af[ma], b0, b1);
                }
            }
        }
        __syncthreads();
    }

    // ---------------- epilogue ----------------
    const int r0 = bm + wy * 64 + (lane >> 2);
    const int c0 = bn + wx * 32 + (lane & 3) * 2;

    #pragma unroll
    for (int ma = 0; ma < 4; ++ma) {
        #pragma unroll
        for (int na = 0; na < 4; ++na) {
            const int row = r0 + ma * 16;
            const int col = c0 + na * 8;
            float* a4 = acc[ma][na];
            if (EPI == 2) {
                __half2 h0 = __floats2half2_rn(gelu_f(a4[0]), gelu_f(a4[1]));
                __half2 h1 = __floats2half2_rn(gelu_f(a4[2]), gelu_f(a4[3]));
                *(__half2*)(Ch + (size_t)row * N + col) = h0;
                *(__half2*)(Ch + (size_t)(row + 8) * N + col) = h1;
            } else {
                float v0 = a4[0], v1 = a4[1], v2 = a4[2], v3 = a4[3];
                if (EPI == 1) {
                    float2 ra = *(const float2*)(R + (size_t)row * N + col);
                    float2 rb = *(const float2*)(R + (size_t)(row + 8) * N + col);
                    v0 += ra.x; v1 += ra.y; v2 += rb.x; v3 += rb.y;
                }
                *(float2*)(Cf + (size_t)row * N + col) = make_float2(v0, v1);
                *(float2*)(Cf + (size_t)(row + 8) * N + col) = make_float2(v2, v3);
            }
        }
    }
}

// ================= causal flash attention (fp32 in, fp16 out) =================
#define BQ  64
#define BKV 64
#define FPAD 65

__global__ void __launch_bounds__(256) flash_attn(
    const float* __restrict__ Q, const float* __restrict__ Kg,
    const float* __restrict__ V, __half* __restrict__ O)
{
    extern __shared__ float sm[];
    float* Qs = sm;
    float* Ks = Qs + 64 * FPAD;
    float* Vs = Ks + 64 * FPAD;
    float* Ps = Vs + 64 * FPAD;

    const int tid = threadIdx.x;
    const int tx = tid & 15;
    const int ty = tid >> 4;
    const int qi = blockIdx.x;
    const int bh = blockIdx.y;
    const int b  = bh >> 4;
    const int h  = bh & 15;
    const size_t qrow0 = (size_t)(b * SEQ + qi * BQ);
    const int fo = h * DK;
    const float scale = 0.125f;

    #pragma unroll
    for (int it = 0; it < 4; it++) {
        int idx = tid + it * 256;
        int r  = idx >> 4;
        int c4 = (idx & 15) << 2;
        float4 qv = *(const float4*)(Q + (qrow0 + r) * D_MODEL + fo + c4);
        Qs[r * FPAD + c4 + 0] = qv.x; Qs[r * FPAD + c4 + 1] = qv.y;
        Qs[r * FPAD + c4 + 2] = qv.z; Qs[r * FPAD + c4 + 3] = qv.w;
    }

    float m_i[4], l_i[4], acc[4][4];
    #pragma unroll
    for (int i = 0; i < 4; i++) {
        m_i[i] = -1e30f; l_i[i] = 0.f;
        #pragma unroll
        for (int j = 0; j < 4; j++) acc[i][j] = 0.f;
    }

    for (int kt = 0; kt <= qi; kt++) {
        #pragma unroll
        for (int it = 0; it < 4; it++) {
            int idx = tid + it * 256;
            int r  = idx >> 4;
            int c4 = (idx & 15) << 2;
            size_t grow = (size_t)(b * SEQ + kt * BKV + r) * D_MODEL + fo + c4;
            float4 kv = *(const float4*)(Kg + grow);
            float4 vv = *(const float4*)(V  + grow);
            Ks[r * FPAD + c4 + 0] = kv.x; Ks[r * FPAD + c4 + 1] = kv.y;
            Ks[r * FPAD + c4 + 2] = kv.z; Ks[r * FPAD + c4 + 3] = kv.w;
            Vs[r * FPAD + c4 + 0] = vv.x; Vs[r * FPAD + c4 + 1] = vv.y;
            Vs[r * FPAD + c4 + 2] = vv.z; Vs[r * FPAD + c4 + 3] = vv.w;
        }
        __syncthreads();

        float s[4][4];
        #pragma unroll
        for (int i = 0; i < 4; i++)
            #pragma unroll
            for (int j = 0; j < 4; j++) s[i][j] = 0.f;

        #pragma unroll 4
        for (int d = 0; d < 64; d++) {
            float a0 = Qs[(ty * 4 + 0) * FPAD + d];
            float a1 = Qs[(ty * 4 + 1) * FPAD + d];
            float a2 = Qs[(ty * 4 + 2) * FPAD + d];
            float a3 = Qs[(ty * 4 + 3) * FPAD + d];
            float b0 = Ks[(tx * 4 + 0) * FPAD + d];
            float b1 = Ks[(tx * 4 + 1) * FPAD + d];
            float b2 = Ks[(tx * 4 + 2) * FPAD + d];
            float b3 = Ks[(tx * 4 + 3) * FPAD + d];
            s[0][0] = fmaf(a0, b0, s[0][0]); s[0][1] = fmaf(a0, b1, s[0][1]);
            s[0][2] = fmaf(a0, b2, s[0][2]); s[0][3] = fmaf(a0, b3, s[0][3]);
            s[1][0] = fmaf(a1, b0, s[1][0]); s[1][1] = fmaf(a1, b1, s[1][1]);
            s[1][2] = fmaf(a1, b2, s[1][2]); s[1][3] = fmaf(a1, b3, s[1][3]);
            s[2][0] = fmaf(a2, b0, s[2][0]); s[2][1] = fmaf(a2, b1, s[2][1]);
            s[2][2] = fmaf(a2, b2, s[2][2]); s[2][3] = fmaf(a2, b3, s[2][3]);
            s[3][0] = fmaf(a3, b0, s[3][0]); s[3][1] = fmaf(a3, b1, s[3][1]);
            s[3][2] = fmaf(a3, b2, s[3][2]); s[3][3] = fmaf(a3, b3, s[3][3]);
        }

        #pragma unroll
        for (int i = 0; i < 4; i++)
            #pragma unroll
            for (int j = 0; j < 4; j++) {
                s[i][j] *= scale;
                if (kt == qi && (tx * 4 + j) > (ty * 4 + i)) s[i][j] = -1e30f;
            }

        #pragma unroll
        for (int i = 0; i < 4; i++) {
            float mloc = fmaxf(fmaxf(s[i][0], s[i][1]), fmaxf(s[i][2], s[i][3]));
            mloc = fmaxf(mloc, __shfl_xor_sync(0xffffffffu, mloc, 8));
            mloc = fmaxf(mloc, __shfl_xor_sync(0xffffffffu, mloc, 4));
            mloc = fmaxf(mloc, __shfl_xor_sync(0xffffffffu, mloc, 2));
            mloc = fmaxf(mloc, __shfl_xor_sync(0xffffffffu, mloc, 1));
            float mnew = fmaxf(m_i[i], mloc);
            float alpha = __expf(m_i[i] - mnew);
            float psum = 0.f;
            #pragma unroll
            for (int j = 0; j < 4; j++) {
                s[i][j] = __expf(s[i][j] - mnew);
                psum += s[i][j];
            }
            psum += __shfl_xor_sync(0xffffffffu, psum, 8);
            psum += __shfl_xor_sync(0xffffffffu, psum, 4);
            psum += __shfl_xor_sync(0xffffffffu, psum, 2);
            psum += __shfl_xor_sync(0xffffffffu, psum, 1);
            l_i[i] = l_i[i] * alpha + psum;
            m_i[i] = mnew;
            #pragma unroll
            for (int j = 0; j < 4; j++) acc[i][j] *= alpha;
            #pragma unroll
            for (int j = 0; j < 4; j++)
                Ps[(ty * 4 + i) * FPAD + tx * 4 + j] = s[i][j];
        }
        __syncthreads();

        #pragma unroll 4
        for (int c = 0; c < 64; c++) {
            float v0 = Vs[c * FPAD + tx * 4 + 0];
            float v1 = Vs[c * FPAD + tx * 4 + 1];
            float v2 = Vs[c * FPAD + tx * 4 + 2];
            float v3 = Vs[c * FPAD + tx * 4 + 3];
            #pragma unroll
            for (int i = 0; i < 4; i++) {
                float p = Ps[(ty * 4 + i) * FPAD + c];
                acc[i][0] = fmaf(p, v0, acc[i][0]);
                acc[i][1] = fmaf(p, v1, acc[i][1]);
                acc[i][2] = fmaf(p, v2, acc[i][2]);
                acc[i][3] = fmaf(p, v3, acc[i][3]);
            }
        }
        __syncthreads();
    }

    #pragma unroll
    for (int i = 0; i < 4; i++) {
        float invl = 1.f / l_i[i];
        __half2 h0 = __floats2half2_rn(acc[i][0] * invl, acc[i][1] * invl);
        __half2 h1 = __floats2half2_rn(acc[i][2] * invl, acc[i][3] * invl);
        __half2* oo = (__half2*)(O + (qrow0 + ty * 4 + i) * D_MODEL + fo + tx * 4);
        oo[0] = h0; oo[1] = h1;
    }
}

// ================= host =================
extern "C" void kernel_launch(void* const* d_in, const int* in_sizes, int n_in,
                              void* d_out, int out_size)
{
    const float* x  = (const float*)d_in[0];
    const float* wq = (const float*)d_in[1];
    const float* wk = (const float*)d_in[2];
    const float* wv = (const float*)d_in[3];
    const float* wo = (const float*)d_in[4];
    const float* w1 = (const float*)d_in[5];
    const float* w2 = (const float*)d_in[6];
    const float* g1 = (const float*)d_in[7];
    const float* g2 = (const float*)d_in[8];
    float* out = (float*)d_out;

    __half *xnh, *atth, *ffhh, *wqh, *wkh, *wvh, *woh, *w1h, *w2h;
    float *q, *k, *v, *x1;
    cudaGetSymbolAddress((void**)&xnh,  g_xnh);
    cudaGetSymbolAddress((void**)&q,    g_q);
    cudaGetSymbolAddress((void**)&k,    g_k);
    cudaGetSymbolAddress((void**)&v,    g_v);
    cudaGetSymbolAddress((void**)&atth, g_atth);
    cudaGetSymbolAddress((void**)&x1,   g_x1);
    cudaGetSymbolAddress((void**)&ffhh, g_ffhh);
    cudaGetSymbolAddress((void**)&wqh,  g_wqh);
    cudaGetSymbolAddress((void**)&wkh,  g_wkh);
    cudaGetSymbolAddress((void**)&wvh,  g_wvh);
    cudaGetSymbolAddress((void**)&woh,  g_woh);
    cudaGetSymbolAddress((void**)&w1h,  g_w1h);
    cudaGetSymbolAddress((void**)&w2h,  g_w2h);

    const int flash_smem = 4 * 64 * FPAD * (int)sizeof(float);
    cudaFuncSetAttribute(flash_attn, cudaFuncAttributeMaxDynamicSharedMemorySize, flash_smem);

    // weight conversions (fp32 -> fp16)
    const int NW = D_MODEL * D_MODEL;
    f2h_kernel<<<NW / 1024, 256>>>(wq, wqh, NW);
    f2h_kernel<<<NW / 1024, 256>>>(wk, wkh, NW);
    f2h_kernel<<<NW / 1024, 256>>>(wv, wvh, NW);
    f2h_kernel<<<NW / 1024, 256>>>(wo, woh, NW);
    f2h_kernel<<<(DFF * D_MODEL) / 1024, 256>>>(w1, w1h, DFF * D_MODEL);
    f2h_kernel<<<(D_MODEL * DFF) / 1024, 256>>>(w2, w2h, D_MODEL * DFF);

    // 1. xn = rmsnorm(x, g1)  (fp16)
    rmsnorm_h_kernel<<<MTOT, 256>>>(x, g1, xnh);

    // 2-4. q,k,v = xn @ W^T  (fp32 out for flash)
    dim3 gproj(D_MODEL / 128, MTOT / 128);
    hgemm_mma<0><<<gproj, 256>>>(xnh, wqh, nullptr, q, nullptr, MTOT, D_MODEL, D_MODEL);
    hgemm_mma<0><<<gproj, 256>>>(xnh, wkh, nullptr, k, nullptr, MTOT, D_MODEL, D_MODEL);
    hgemm_mma<0><<<gproj, 256>>>(xnh, wvh, nullptr, v, nullptr, MTOT, D_MODEL, D_MODEL);

    // 5. att = causal_attention(q,k,v)  (fp16 out)
    flash_attn<<<dim3(SEQ / BQ, BATCH * NHEAD), 256, flash_smem>>>(q, k, v, atth);

    // 6. x1 = x + att @ wo^T
    hgemm_mma<1><<<gproj, 256>>>(atth, woh, x, x1, nullptr, MTOT, D_MODEL, D_MODEL);

    // 7. xn = rmsnorm(x1, g2)  (fp16)
    rmsnorm_h_kernel<<<MTOT, 256>>>(x1, g2, xnh);

    // 8. ffh = gelu(xn @ w1^T)  (fp16 out)
    dim3 gff1(DFF / 128, MTOT / 128);
    hgemm_mma<2><<<gff1, 256>>>(xnh, w1h, nullptr, nullptr, ffhh, MTOT, DFF, D_MODEL);

    // 9. out = x1 + ffh @ w2^T
    hgemm_mma<1><<<gproj, 256>>>(ffhh, w2h, x1, out, nullptr, MTOT, D_MODEL, DFF);
}

// round 7
// speedup vs baseline: 5.9209x; 2.1168x over previous
#include <cuda_runtime.h>
#include <cuda_fp16.h>
#include <math.h>
#include <stdint.h>

#define D_MODEL 1024
#define NHEAD   16
#define DK      64
#define DFF     4096
#define BATCH   2
#define SEQ     2048
#define MTOT    (BATCH*SEQ)   /* 4096 */
#define EPS_RMS 1e-5f
#define QKV_LD  (3*D_MODEL)   /* 3072 */

// ================= low-level helpers (baseline PTX ISA) =================
__device__ __forceinline__ uint32_t smem_to_u32(const void* p) {
    uint32_t a;
    asm("{ .reg .u64 t; cvta.to.shared.u64 t, %1; cvt.u32.u64 %0, t; }" : "=r"(a) : "l"(p));
    return a;
}
__device__ __forceinline__ void cp_async16(uint32_t dst, const void* src) {
    asm volatile("cp.async.cg.shared.global [%0], [%1], 16;" :: "r"(dst), "l"(src));
}
#define CP_COMMIT() asm volatile("cp.async.commit_group;" ::: "memory")
#define CP_WAIT(n)  asm volatile("cp.async.wait_group %0;" :: "n"(n) : "memory")

__device__ __forceinline__ void ldsm_x4(uint32_t& r0, uint32_t& r1, uint32_t& r2, uint32_t& r3,
                                        uint32_t addr) {
    asm volatile("ldmatrix.sync.aligned.m8n8.x4.shared.b16 {%0,%1,%2,%3}, [%4];"
        : "=r"(r0), "=r"(r1), "=r"(r2), "=r"(r3) : "r"(addr));
}
__device__ __forceinline__ void ldsm_x4_t(uint32_t& r0, uint32_t& r1, uint32_t& r2, uint32_t& r3,
                                          uint32_t addr) {
    asm volatile("ldmatrix.sync.aligned.m8n8.x4.trans.shared.b16 {%0,%1,%2,%3}, [%4];"
        : "=r"(r0), "=r"(r1), "=r"(r2), "=r"(r3) : "r"(addr));
}
__device__ __forceinline__ void mma16816(float* c, const uint32_t* a, uint32_t b0, uint32_t b1) {
    asm volatile("mma.sync.aligned.m16n8k16.row.col.f32.f16.f16.f32 "
        "{%0,%1,%2,%3}, {%4,%5,%6,%7}, {%8,%9}, {%0,%1,%2,%3};"
        : "+f"(c[0]), "+f"(c[1]), "+f"(c[2]), "+f"(c[3])
        : "r"(a[0]), "r"(a[1]), "r"(a[2]), "r"(a[3]), "r"(b0), "r"(b1));
}
__device__ __forceinline__ uint32_t packh2(float a, float b) {
    __half2 h = __floats2half2_rn(a, b);
    return *(uint32_t*)&h;
}

// ================= scratch buffers =================
__device__ __half g_xnh [MTOT*D_MODEL];
__device__ __half g_qkvh[MTOT*QKV_LD];
__device__ __half g_atth[MTOT*D_MODEL];
__device__ float  g_x1  [MTOT*D_MODEL];
__device__ __half g_ffhh[MTOT*DFF];
__device__ __half g_w3h [3*D_MODEL*D_MODEL];   /* concat(wq, wk, wv) */
__device__ __half g_woh [D_MODEL*D_MODEL];
__device__ __half g_w1h [DFF*D_MODEL];
__device__ __half g_w2h [D_MODEL*DFF];

// ================= fp32 -> fp16 convert =================
__global__ void __launch_bounds__(256) f2h_kernel(
    const float* __restrict__ a, __half* __restrict__ b, int n)
{
    int i = (blockIdx.x * 256 + threadIdx.x) * 4;
    if (i < n) {
        float4 v = *(const float4*)(a + i);
        ((__half2*)(b + i))[0] = __floats2half2_rn(v.x, v.y);
        ((__half2*)(b + i))[1] = __floats2half2_rn(v.z, v.w);
    }
}

// ================= RMSNorm -> fp16 =================
__global__ void __launch_bounds__(256) rmsnorm_h_kernel(
    const float* __restrict__ x, const float* __restrict__ g, __half* __restrict__ y)
{
    const int row = blockIdx.x;
    const float4* x4 = (const float4*)(x + (size_t)row * D_MODEL);
    const float4* g4 = (const float4*)g;

    float4 v = x4[threadIdx.x];
    float s = v.x*v.x + v.y*v.y + v.z*v.z + v.w*v.w;

    #pragma unroll
    for (int m = 16; m; m >>= 1) s += __shfl_xor_sync(0xffffffffu, s, m);

    __shared__ float red[8];
    int warp = threadIdx.x >> 5, lane = threadIdx.x & 31;
    if (lane == 0) red[warp] = s;
    __syncthreads();
    if (warp == 0) {
        float t = (lane < 8) ? red[lane] : 0.f;
        t += __shfl_xor_sync(0xffffffffu, t, 4);
        t += __shfl_xor_sync(0xffffffffu, t, 2);
        t += __shfl_xor_sync(0xffffffffu, t, 1);
        if (lane == 0) red[0] = t;
    }
    __syncthreads();

    float rms = rsqrtf(red[0] * (1.0f / D_MODEL) + EPS_RMS);
    float4 gg = g4[threadIdx.x];
    __half2* yo = (__half2*)(y + (size_t)row * D_MODEL + threadIdx.x * 4);
    yo[0] = __floats2half2_rn(v.x * rms * gg.x, v.y * rms * gg.y);
    yo[1] = __floats2half2_rn(v.z * rms * gg.z, v.w * rms * gg.w);
}

// ================= GELU =================
__device__ __forceinline__ float gelu_f(float v) {
    return 0.5f * v * (1.0f + erff(v * 0.70710678118654752f));
}

// ====== HGEMM via mma.sync: C[M,N] = A[M,K] * B[N,K]^T (torch Linear NT) ======
// EPI: 0 = fp32 out; 1 = fp32 out + residual; 2 = fp16 out + GELU; 3 = fp16 out
#define KCH   32
#define SPAD  40

__device__ __forceinline__ void load_chunk_ca(
    const __half* __restrict__ G, int base_row, int K, int k0, int tid, uint32_t s_stage)
{
    #pragma unroll
    for (int i = 0; i < 2; i++) {
        int idx = tid + i * 256;
        int row = idx >> 2, seg = idx & 3;
        const __half* src = G + (size_t)(base_row + row) * K + k0 + seg * 8;
        uint32_t dst = s_stage + (uint32_t)(row * SPAD + seg * 8) * 2;
        cp_async16(dst, src);
    }
}

template <int EPI>
__global__ void __launch_bounds__(256) hgemm_mma(
    const __half* __restrict__ A, const __half* __restrict__ B,
    const float* __restrict__ R, float* __restrict__ Cf, __half* __restrict__ Ch,
    int M, int N, int K)
{
    __shared__ __half As[2][128][SPAD];
    __shared__ __half Bs[2][128][SPAD];

    const int tid = threadIdx.x;
    const int lane = tid & 31;
    const int wid = tid >> 5;
    const int wy = wid & 1;
    const int wx = wid >> 1;
    const int bm = blockIdx.y * 128;
    const int bn = blockIdx.x * 128;

    const uint32_t a_base = smem_to_u32(&As[0][0][0]);
    const uint32_t b_base = smem_to_u32(&Bs[0][0][0]);
    const uint32_t stage_bytes = 128 * SPAD * 2;

    const int lrow = lane & 15;
    const int koff = (lane >> 4) * 8;

    float acc[4][4][4];
    #pragma unroll
    for (int i = 0; i < 4; i++)
        #pragma unroll
        for (int j = 0; j < 4; j++)
            #pragma unroll
            for (int r = 0; r < 4; r++) acc[i][j][r] = 0.f;

    const int nch = K / KCH;

    load_chunk_ca(A, bm, K, 0, tid, a_base);
    load_chunk_ca(B, bn, K, 0, tid, b_base);
    CP_COMMIT();

    for (int c = 0; c < nch; ++c) {
        const int st = c & 1;
        if (c + 1 < nch) {
            const uint32_t off = (uint32_t)(st ^ 1) * stage_bytes;
            load_chunk_ca(A, bm, K, (c + 1) * KCH, tid, a_base + off);
            load_chunk_ca(B, bn, K, (c + 1) * KCH, tid, b_base + off);
            CP_COMMIT();
            CP_WAIT(1);
        } else {
            CP_WAIT(0);
        }
        __syncthreads();

        const uint32_t a_st = a_base + (uint32_t)st * stage_bytes;
        const uint32_t b_st = b_base + (uint32_t)st * stage_bytes;

        #pragma unroll
        for (int ks = 0; ks < 2; ++ks) {
            uint32_t af[4][4];
            #pragma unroll
            for (int ma = 0; ma < 4; ++ma) {
                uint32_t addr = a_st +
                    (uint32_t)((wy * 64 + ma * 16 + lrow) * SPAD + ks * 16 + koff) * 2;
                ldsm_x4(af[ma][0], af[ma][1], af[ma][2], af[ma][3], addr);
            }
            uint32_t bf[2][4];
            #pragma unroll
            for (int nb = 0; nb < 2; ++nb) {
                uint32_t addr = b_st +
                    (uint32_t)((wx * 32 + nb * 16 + lrow) * SPAD + ks * 16 + koff) * 2;
                ldsm_x4(bf[nb][0], bf[nb][1], bf[nb][2], bf[nb][3], addr);
            }
            #pragma unroll
            for (int ma = 0; ma < 4; ++ma) {
                #pragma unroll
                for (int na = 0; na < 4; ++na) {
                    const uint32_t b0 = bf[na >> 1][(na & 1)];
                    const uint32_t b1 = bf[na >> 1][(na & 1) + 2];
                    mma16816(acc[ma][na], af[ma], b0, b1);
                }
            }
        }
        __syncthreads();
    }

    const int r0 = bm + wy * 64 + (lane >> 2);
    const int c0 = bn + wx * 32 + (lane & 3) * 2;

    #pragma unroll
    for (int ma = 0; ma < 4; ++ma) {
        #pragma unroll
        for (int na = 0; na < 4; ++na) {
            const int row = r0 + ma * 16;
            const int col = c0 + na * 8;
            float* a4 = acc[ma][na];
            if (EPI == 2) {
                *(__half2*)(Ch + (size_t)row * N + col) =
                    __floats2half2_rn(gelu_f(a4[0]), gelu_f(a4[1]));
                *(__half2*)(Ch + (size_t)(row + 8) * N + col) =
                    __floats2half2_rn(gelu_f(a4[2]), gelu_f(a4[3]));
            } else if (EPI == 3) {
                *(__half2*)(Ch + (size_t)row * N + col) = __floats2half2_rn(a4[0], a4[1]);
                *(__half2*)(Ch + (size_t)(row + 8) * N + col) = __floats2half2_rn(a4[2], a4[3]);
            } else {
                float v0 = a4[0], v1 = a4[1], v2 = a4[2], v3 = a4[3];
                if (EPI == 1) {
                    float2 ra = *(const float2*)(R + (size_t)row * N + col);
                    float2 rb = *(const float2*)(R + (size_t)(row + 8) * N + col);
                    v0 += ra.x; v1 += ra.y; v2 += rb.x; v3 += rb.y;
                }
                *(float2*)(Cf + (size_t)row * N + col) = make_float2(v0, v1);
                *(float2*)(Cf + (size_t)(row + 8) * N + col) = make_float2(v2, v3);
            }
        }
    }
}

// ========== flash attention via mma.sync (fp16 in/out, fp32 accum) ==========
// 128 threads = 4 warps; CTA = 64 q-rows; warp = 16 q-rows x 64 kv.
// K/V tiles double-buffered via cp.async. Causal; qi reversed for load balance.
// NOTE: tile row = 64 halves = 8 x 16B segments -> 512 cp.async per tile.
#define FP2 72   /* padded row: 64 + 8 halves */

__global__ void __launch_bounds__(128) flash_mma(
    const __half* __restrict__ QKV, __half* __restrict__ O)
{
    __shared__ __half Qs[64][FP2];
    __shared__ __half Ks[2][64][FP2];
    __shared__ __half Vs[2][64][FP2];

    const int tid = threadIdx.x;
    const int lane = tid & 31;
    const int wid = tid >> 5;
    const int qi = (int)(gridDim.x - 1 - blockIdx.x);   // longest first
    const int bh = blockIdx.y;
    const int b = bh >> 4, h = bh & 15;
    const size_t qrow0 = (size_t)(b * SEQ + qi * 64);
    const __half* Qg = QKV + qrow0 * QKV_LD + h * DK;
    const __half* Kg = QKV + (size_t)(b * SEQ) * QKV_LD + D_MODEL + h * DK;
    const __half* Vg = QKV + (size_t)(b * SEQ) * QKV_LD + 2 * D_MODEL + h * DK;

    const uint32_t qs_b = smem_to_u32(&Qs[0][0]);
    const uint32_t ks_b = smem_to_u32(&Ks[0][0][0]);
    const uint32_t vs_b = smem_to_u32(&Vs[0][0][0]);
    const uint32_t kv_stage = 64 * FP2 * 2;

    // load Q tile: 64 rows x 8 segs = 512 transfers
    #pragma unroll
    for (int i = 0; i < 4; i++) {
        int idx = tid + i * 128;
        int r = idx >> 3, s = idx & 7;
        cp_async16(qs_b + (uint32_t)(r * FP2 + s * 8) * 2, Qg + (size_t)r * QKV_LD + s * 8);
    }
    CP_COMMIT();
    // prefetch kv tile 0 -> stage 0
    #pragma unroll
    for (int i = 0; i < 4; i++) {
        int idx = tid + i * 128;
        int r = idx >> 3, s = idx & 7;
        size_t go = (size_t)r * QKV_LD + s * 8;
        cp_async16(ks_b + (uint32_t)(r * FP2 + s * 8) * 2, Kg + go);
        cp_async16(vs_b + (uint32_t)(r * FP2 + s * 8) * 2, Vg + go);
    }
    CP_COMMIT();
    CP_WAIT(1);          // Q done
    __syncthreads();

    // Q fragments, cached for whole kernel
    uint32_t qf[4][4];
    #pragma unroll
    for (int ks = 0; ks < 4; ks++) {
        uint32_t addr = qs_b +
            (uint32_t)((wid * 16 + (lane & 15)) * FP2 + ks * 16 + (lane >> 4) * 8) * 2;
        ldsm_x4(qf[ks][0], qf[ks][1], qf[ks][2], qf[ks][3], addr);
    }

    float o[8][4];
    #pragma unroll
    for (int j = 0; j < 8; j++)
        #pragma unroll
        for (int r = 0; r < 4; r++) o[j][r] = 0.f;
    float m0 = -1e30f, m1 = -1e30f, l0 = 0.f, l1 = 0.f;
    const float scale = 0.125f;

    for (int kt = 0; kt <= qi; ++kt) {
        const int st = kt & 1;
        __syncthreads();                 // readers of stage st (iter kt-2) done
        if (kt < qi) {
            const uint32_t so = (uint32_t)(st ^ 1) * kv_stage;
            #pragma unroll
            for (int i = 0; i < 4; i++) {
                int idx = tid + i * 128;
                int r = idx >> 3, s = idx & 7;
                size_t go = (size_t)((kt + 1) * 64 + r) * QKV_LD + s * 8;
                cp_async16(ks_b + so + (uint32_t)(r * FP2 + s * 8) * 2, Kg + go);
                cp_async16(vs_b + so + (uint32_t)(r * FP2 + s * 8) * 2, Vg + go);
            }
            CP_COMMIT();
            CP_WAIT(1);                  // current stage complete
        } else {
            CP_WAIT(0);
        }
        __syncthreads();

        // ---- S = Q K^T ----
        float sf[8][4];
        #pragma unroll
        for (int j = 0; j < 8; j++)
            #pragma unroll
            for (int r = 0; r < 4; r++) sf[j][r] = 0.f;

        const uint32_t ks_st = ks_b + (uint32_t)st * kv_stage;
        #pragma unroll
        for (int ks = 0; ks < 4; ks++) {
            #pragma unroll
            for (int nb = 0; nb < 4; nb++) {
                uint32_t r0, r1, r2, r3;
                uint32_t addr = ks_st +
                    (uint32_t)((nb * 16 + (lane & 15)) * FP2 + ks * 16 + (lane >> 4) * 8) * 2;
                ldsm_x4(r0, r1, r2, r3, addr);
                mma16816(sf[nb * 2 + 0], qf[ks], r0, r2);
                mma16816(sf[nb * 2 + 1], qf[ks], r1, r3);
            }
        }

        // ---- scale + causal mask (diagonal tile only) ----
        if (kt == qi) {
            const int rg0 = wid * 16 + (lane >> 2);
            #pragma unroll
            for (int j = 0; j < 8; j++) {
                const int c0 = j * 8 + (lane & 3) * 2;
                sf[j][0] = (c0     > rg0    ) ? -1e30f : sf[j][0] * scale;
                sf[j][1] = (c0 + 1 > rg0    ) ? -1e30f : sf[j][1] * scale;
                sf[j][2] = (c0     > rg0 + 8) ? -1e30f : sf[j][2] * scale;
                sf[j][3] = (c0 + 1 > rg0 + 8) ? -1e30f : sf[j][3] * scale;
            }
        } else {
            #pragma unroll
            for (int j = 0; j < 8; j++) {
                sf[j][0] *= scale; sf[j][1] *= scale;
                sf[j][2] *= scale; sf[j][3] *= scale;
            }
        }

        // ---- online softmax ----
        float t0 = -1e30f, t1 = -1e30f;
        #pragma unroll
        for (int j = 0; j < 8; j++) {
            t0 = fmaxf(t0, fmaxf(sf[j][0], sf[j][1]));
            t1 = fmaxf(t1, fmaxf(sf[j][2], sf[j][3]));
        }
        t0 = fmaxf(t0, __shfl_xor_sync(0xffffffffu, t0, 1));
        t0 = fmaxf(t0, __shfl_xor_sync(0xffffffffu, t0, 2));
        t1 = fmaxf(t1, __shfl_xor_sync(0xffffffffu, t1, 1));
        t1 = fmaxf(t1, __shfl_xor_sync(0xffffffffu, t1, 2));

        const float mn0 = fmaxf(m0, t0), mn1 = fmaxf(m1, t1);
        const float a0 = __expf(m0 - mn0), a1 = __expf(m1 - mn1);
        float ps0 = 0.f, ps1 = 0.f;
        #pragma unroll
        for (int j = 0; j < 8; j++) {
            sf[j][0] = __expf(sf[j][0] - mn0);
            sf[j][1] = __expf(sf[j][1] - mn0);
            sf[j][2] = __expf(sf[j][2] - mn1);
            sf[j][3] = __expf(sf[j][3] - mn1);
            ps0 += sf[j][0] + sf[j][1];
            ps1 += sf[j][2] + sf[j][3];
        }
        ps0 += __shfl_xor_sync(0xffffffffu, ps0, 1);
        ps0 += __shfl_xor_sync(0xffffffffu, ps0, 2);
        ps1 += __shfl_xor_sync(0xffffffffu, ps1, 1);
        ps1 += __shfl_xor_sync(0xffffffffu, ps1, 2);
        l0 = l0 * a0 + ps0; l1 = l1 * a1 + ps1;
        m0 = mn0; m1 = mn1;
        #pragma unroll
        for (int j = 0; j < 8; j++) {
            o[j][0] *= a0; o[j][1] *= a0;
            o[j][2] *= a1; o[j][3] *= a1;
        }

        // ---- P -> fp16 A-fragments (C->A layout identity on 16x16 tiles) ----
        uint32_t pf[4][4];
        #pragma unroll
        for (int kk = 0; kk < 4; kk++) {
            pf[kk][0] = packh2(sf[2*kk][0],   sf[2*kk][1]);
            pf[kk][1] = packh2(sf[2*kk][2],   sf[2*kk][3]);
            pf[kk][2] = packh2(sf[2*kk+1][0], sf[2*kk+1][1]);
            pf[kk][3] = packh2(sf[2*kk+1][2], sf[2*kk+1][3]);
        }

        // ---- O += P V ----
        const uint32_t vs_st = vs_b + (uint32_t)st * kv_stage;
        #pragma unroll
        for (int kk = 0; kk < 4; kk++) {
            #pragma unroll
            for (int ns = 0; ns < 4; ns++) {
                uint32_t v0, v1, v2, v3;
                uint32_t addr = vs_st +
                    (uint32_t)((kk * 16 + (lane & 7) + 8 * ((lane >> 3) & 1)) * FP2 +
                               ns * 16 + 8 * (lane >> 4)) * 2;
                ldsm_x4_t(v0, v1, v2, v3, addr);
                mma16816(o[2 * ns + 0], pf[kk], v0, v1);
                mma16816(o[2 * ns + 1], pf[kk], v2, v3);
            }
        }
    }

    // ---- epilogue ----
    const float i0 = 1.f / l0, i1 = 1.f / l1;
    const size_t gr0 = qrow0 + wid * 16 + (lane >> 2);
    #pragma unroll
    for (int j = 0; j < 8; j++) {
        const int col = h * DK + j * 8 + (lane & 3) * 2;
        *(__half2*)(O + gr0 * D_MODEL + col) =
            __floats2half2_rn(o[j][0] * i0, o[j][1] * i0);
        *(__half2*)(O + (gr0 + 8) * D_MODEL + col) =
            __floats2half2_rn(o[j][2] * i1, o[j][3] * i1);
    }
}

// ================= host =================
extern "C" void kernel_launch(void* const* d_in, const int* in_sizes, int n_in,
                              void* d_out, int out_size)
{
    const float* x  = (const float*)d_in[0];
    const float* wq = (const float*)d_in[1];
    const float* wk = (const float*)d_in[2];
    const float* wv = (const float*)d_in[3];
    const float* wo = (const float*)d_in[4];
    const float* w1 = (const float*)d_in[5];
    const float* w2 = (const float*)d_in[6];
    const float* g1 = (const float*)d_in[7];
    const float* g2 = (const float*)d_in[8];
    float* out = (float*)d_out;

    __half *xnh, *qkvh, *atth, *ffhh, *w3h, *woh, *w1h, *w2h;
    float *x1;
    cudaGetSymbolAddress((void**)&xnh,  g_xnh);
    cudaGetSymbolAddress((void**)&qkvh, g_qkvh);
    cudaGetSymbolAddress((void**)&atth, g_atth);
    cudaGetSymbolAddress((void**)&x1,   g_x1);
    cudaGetSymbolAddress((void**)&ffhh, g_ffhh);
    cudaGetSymbolAddress((void**)&w3h,  g_w3h);
    cudaGetSymbolAddress((void**)&woh,  g_woh);
    cudaGetSymbolAddress((void**)&w1h,  g_w1h);
    cudaGetSymbolAddress((void**)&w2h,  g_w2h);

    // weight conversions (fp32 -> fp16); wq|wk|wv concatenated along N
    const int NW = D_MODEL * D_MODEL;
    f2h_kernel<<<NW / 1024, 256>>>(wq, w3h,          NW);
    f2h_kernel<<<NW / 1024, 256>>>(wk, w3h + NW,     NW);
    f2h_kernel<<<NW / 1024, 256>>>(wv, w3h + 2*NW,   NW);
    f2h_kernel<<<NW / 1024, 256>>>(wo, woh, NW);
    f2h_kernel<<<(DFF * D_MODEL) / 1024, 256>>>(w1, w1h, DFF * D_MODEL);
    f2h_kernel<<<(D_MODEL * DFF) / 1024, 256>>>(w2, w2h, D_MODEL * DFF);

    // 1. xn = rmsnorm(x, g1)
    rmsnorm_h_kernel<<<MTOT, 256>>>(x, g1, xnh);

    // 2. qkv = xn @ [wq|wk|wv]^T   (fused, fp16 out)
    dim3 gqkv(QKV_LD / 128, MTOT / 128);
    hgemm_mma<3><<<gqkv, 256>>>(xnh, w3h, nullptr, nullptr, qkvh, MTOT, QKV_LD, D_MODEL);

    // 3. att = causal_attention(q,k,v)  (tensor-core flash)
    flash_mma<<<dim3(SEQ / 64, BATCH * NHEAD), 128>>>(qkvh, atth);

    // 4. x1 = x + att @ wo^T
    dim3 gproj(D_MODEL / 128, MTOT / 128);
    hgemm_mma<1><<<gproj, 256>>>(atth, woh, x, x1, nullptr, MTOT, D_MODEL, D_MODEL);

    // 5. xn = rmsnorm(x1, g2)
    rmsnorm_h_kernel<<<MTOT, 256>>>(x1, g2, xnh);

    // 6. ffh = gelu(xn @ w1^T)
    dim3 gff1(DFF / 128, MTOT / 128);
    hgemm_mma<2><<<gff1, 256>>>(xnh, w1h, nullptr, nullptr, ffhh, MTOT, DFF, D_MODEL);

    // 7. out = x1 + ffh @ w2^T
    hgemm_mma<1><<<gproj, 256>>>(ffhh, w2h, x1, out, nullptr, MTOT, D_MODEL, DFF);
}

// round 8
// speedup vs baseline: 6.0410x; 1.0203x over previous
#include <cuda_runtime.h>
#include <cuda_fp16.h>
#include <math.h>
#include <stdint.h>

#define D_MODEL 1024
#define NHEAD   16
#define DK      64
#define DFF     4096
#define BATCH   2
#define SEQ     2048
#define MTOT    (BATCH*SEQ)   /* 4096 */
#define EPS_RMS 1e-5f
#define QKV_LD  (3*D_MODEL)   /* 3072 */

// ================= low-level helpers (baseline PTX ISA) =================
__device__ __forceinline__ uint32_t smem_to_u32(const void* p) {
    uint32_t a;
    asm("{ .reg .u64 t; cvta.to.shared.u64 t, %1; cvt.u32.u64 %0, t; }" : "=r"(a) : "l"(p));
    return a;
}
__device__ __forceinline__ void cp_async16(uint32_t dst, const void* src) {
    asm volatile("cp.async.cg.shared.global [%0], [%1], 16;" :: "r"(dst), "l"(src));
}
#define CP_COMMIT() asm volatile("cp.async.commit_group;" ::: "memory")
#define CP_WAIT(n)  asm volatile("cp.async.wait_group %0;" :: "n"(n) : "memory")

__device__ __forceinline__ void ldsm_x4(uint32_t& r0, uint32_t& r1, uint32_t& r2, uint32_t& r3,
                                        uint32_t addr) {
    asm volatile("ldmatrix.sync.aligned.m8n8.x4.shared.b16 {%0,%1,%2,%3}, [%4];"
        : "=r"(r0), "=r"(r1), "=r"(r2), "=r"(r3) : "r"(addr));
}
__device__ __forceinline__ void ldsm_x4_t(uint32_t& r0, uint32_t& r1, uint32_t& r2, uint32_t& r3,
                                          uint32_t addr) {
    asm volatile("ldmatrix.sync.aligned.m8n8.x4.trans.shared.b16 {%0,%1,%2,%3}, [%4];"
        : "=r"(r0), "=r"(r1), "=r"(r2), "=r"(r3) : "r"(addr));
}
__device__ __forceinline__ void mma16816(float* c, const uint32_t* a, uint32_t b0, uint32_t b1) {
    asm volatile("mma.sync.aligned.m16n8k16.row.col.f32.f16.f16.f32 "
        "{%0,%1,%2,%3}, {%4,%5,%6,%7}, {%8,%9}, {%0,%1,%2,%3};"
        : "+f"(c[0]), "+f"(c[1]), "+f"(c[2]), "+f"(c[3])
        : "r"(a[0]), "r"(a[1]), "r"(a[2]), "r"(a[3]), "r"(b0), "r"(b1));
}
__device__ __forceinline__ uint32_t packh2(float a, float b) {
    __half2 h = __floats2half2_rn(a, b);
    return *(uint32_t*)&h;
}

// ================= scratch buffers =================
__device__ __half g_xnh [MTOT*D_MODEL];
__device__ __half g_qkvh[MTOT*QKV_LD];
__device__ __half g_atth[MTOT*D_MODEL];
__device__ float  g_x1  [MTOT*D_MODEL];
__device__ __half g_ffhh[MTOT*DFF];
__device__ __half g_w3h [3*D_MODEL*D_MODEL];   /* concat(wq, wk, wv) */
__device__ __half g_woh [D_MODEL*D_MODEL];
__device__ __half g_w1h [DFF*D_MODEL];
__device__ __half g_w2h [D_MODEL*DFF];

// ================= fp32 -> fp16 convert =================
__global__ void __launch_bounds__(256) f2h_kernel(
    const float* __restrict__ a, __half* __restrict__ b, int n)
{
    int i = (blockIdx.x * 256 + threadIdx.x) * 4;
    if (i < n) {
        float4 v = *(const float4*)(a + i);
        ((__half2*)(b + i))[0] = __floats2half2_rn(v.x, v.y);
        ((__half2*)(b + i))[1] = __floats2half2_rn(v.z, v.w);
    }
}

// ================= RMSNorm -> fp16 =================
__global__ void __launch_bounds__(256) rmsnorm_h_kernel(
    const float* __restrict__ x, const float* __restrict__ g, __half* __restrict__ y)
{
    const int row = blockIdx.x;
    const float4* x4 = (const float4*)(x + (size_t)row * D_MODEL);
    const float4* g4 = (const float4*)g;

    float4 v = x4[threadIdx.x];
    float s = v.x*v.x + v.y*v.y + v.z*v.z + v.w*v.w;

    #pragma unroll
    for (int m = 16; m; m >>= 1) s += __shfl_xor_sync(0xffffffffu, s, m);

    __shared__ float red[8];
    int warp = threadIdx.x >> 5, lane = threadIdx.x & 31;
    if (lane == 0) red[warp] = s;
    __syncthreads();
    if (warp == 0) {
        float t = (lane < 8) ? red[lane] : 0.f;
        t += __shfl_xor_sync(0xffffffffu, t, 4);
        t += __shfl_xor_sync(0xffffffffu, t, 2);
        t += __shfl_xor_sync(0xffffffffu, t, 1);
        if (lane == 0) red[0] = t;
    }
    __syncthreads();

    float rms = rsqrtf(red[0] * (1.0f / D_MODEL) + EPS_RMS);
    float4 gg = g4[threadIdx.x];
    __half2* yo = (__half2*)(y + (size_t)row * D_MODEL + threadIdx.x * 4);
    yo[0] = __floats2half2_rn(v.x * rms * gg.x, v.y * rms * gg.y);
    yo[1] = __floats2half2_rn(v.z * rms * gg.z, v.w * rms * gg.w);
}

// ================= GELU =================
__device__ __forceinline__ float gelu_f(float v) {
    return 0.5f * v * (1.0f + erff(v * 0.70710678118654752f));
}

// ====== HGEMM v2: 128 threads, warp tile 64x64, 3-stage cp.async ======
// C[M,N] = A[M,K] * B[N,K]^T. EPI: 1 = fp32 + residual; 2 = fp16 GELU; 3 = fp16
#define KCH    32
#define SPAD   40
#define HG_STAGE_B (128 * SPAD * 2)       /* 10240 B per matrix per stage */
#define HG_SMEM    (6 * HG_STAGE_B)       /* 3 stages x (A,B) = 61440 B  */

__device__ __forceinline__ void hg_load(
    const __half* __restrict__ G, int base_row, int K, int k0, int tid, uint32_t s_stage)
{
    #pragma unroll
    for (int i = 0; i < 4; i++) {
        int idx = tid + i * 128;              // 0..511
        int row = idx >> 2, seg = idx & 3;    // 128 rows x 4 16B-segs
        const __half* src = G + (size_t)(base_row + row) * K + k0 + seg * 8;
        cp_async16(s_stage + (uint32_t)(row * SPAD + seg * 8) * 2, src);
    }
}

template <int EPI>
__global__ void __launch_bounds__(128) hgemm_mma(
    const __half* __restrict__ A, const __half* __restrict__ B,
    const float* __restrict__ R, float* __restrict__ Cf, __half* __restrict__ Ch,
    int M, int N, int K)
{
    extern __shared__ __half hsm[];
    const uint32_t a_base = smem_to_u32(hsm);
    const uint32_t b_base = a_base + 3 * HG_STAGE_B;

    const int tid = threadIdx.x;
    const int lane = tid & 31;
    const int wid = tid >> 5;
    const int wy = wid & 1;        // M offset 64*wy
    const int wx = wid >> 1;       // N offset 64*wx
    const int bm = blockIdx.y * 128;
    const int bn = blockIdx.x * 128;

    const int lrow = lane & 15;
    const int koff = (lane >> 4) * 8;

    float acc[4][8][4];
    #pragma unroll
    for (int i = 0; i < 4; i++)
        #pragma unroll
        for (int j = 0; j < 8; j++)
            #pragma unroll
            for (int r = 0; r < 4; r++) acc[i][j][r] = 0.f;

    const int nch = K / KCH;      // >= 32 for all our shapes

    // prologue: chunks 0,1 -> stages 0,1
    hg_load(A, bm, K, 0, tid, a_base);
    hg_load(B, bn, K, 0, tid, b_base);
    CP_COMMIT();
    hg_load(A, bm, K, KCH, tid, a_base + HG_STAGE_B);
    hg_load(B, bn, K, KCH, tid, b_base + HG_STAGE_B);
    CP_COMMIT();

    int st = 0;
    for (int c = 0; c < nch; ++c) {
        if (c + 2 < nch) {
            const int sp = (st + 2 >= 3) ? st - 1 : st + 2;
            hg_load(A, bm, K, (c + 2) * KCH, tid, a_base + (uint32_t)sp * HG_STAGE_B);
            hg_load(B, bn, K, (c + 2) * KCH, tid, b_base + (uint32_t)sp * HG_STAGE_B);
            CP_COMMIT();
            CP_WAIT(2);
        } else if (c + 1 < nch) {
            CP_WAIT(1);
        } else {
            CP_WAIT(0);
        }
        __syncthreads();

        const uint32_t a_st = a_base + (uint32_t)st * HG_STAGE_B;
        const uint32_t b_st = b_base + (uint32_t)st * HG_STAGE_B;

        #pragma unroll
        for (int ks = 0; ks < 2; ++ks) {
            uint32_t af[4][4];
            #pragma unroll
            for (int ma = 0; ma < 4; ++ma) {
                uint32_t addr = a_st +
                    (uint32_t)((wy * 64 + ma * 16 + lrow) * SPAD + ks * 16 + koff) * 2;
                ldsm_x4(af[ma][0], af[ma][1], af[ma][2], af[ma][3], addr);
            }
            uint32_t bf[4][4];
            #pragma unroll
            for (int nb = 0; nb < 4; ++nb) {
                uint32_t addr = b_st +
                    (uint32_t)((wx * 64 + nb * 16 + lrow) * SPAD + ks * 16 + koff) * 2;
                ldsm_x4(bf[nb][0], bf[nb][1], bf[nb][2], bf[nb][3], addr);
            }
            #pragma unroll
            for (int ma = 0; ma < 4; ++ma) {
                #pragma unroll
                for (int na = 0; na < 8; ++na) {
                    const uint32_t b0 = bf[na >> 1][(na & 1)];
                    const uint32_t b1 = bf[na >> 1][(na & 1) + 2];
                    mma16816(acc[ma][na], af[ma], b0, b1);
                }
            }
        }
        __syncthreads();
        st = (st + 1 >= 3) ? 0 : st + 1;
    }

    // ---------------- epilogue ----------------
    const int r0 = bm + wy * 64 + (lane >> 2);
    const int c0 = bn + wx * 64 + (lane & 3) * 2;

    #pragma unroll
    for (int ma = 0; ma < 4; ++ma) {
        #pragma unroll
        for (int na = 0; na < 8; ++na) {
            const int row = r0 + ma * 16;
            const int col = c0 + na * 8;
            float* a4 = acc[ma][na];
            if (EPI == 2) {
                *(__half2*)(Ch + (size_t)row * N + col) =
                    __floats2half2_rn(gelu_f(a4[0]), gelu_f(a4[1]));
                *(__half2*)(Ch + (size_t)(row + 8) * N + col) =
                    __floats2half2_rn(gelu_f(a4[2]), gelu_f(a4[3]));
            } else if (EPI == 3) {
                *(__half2*)(Ch + (size_t)row * N + col) = __floats2half2_rn(a4[0], a4[1]);
                *(__half2*)(Ch + (size_t)(row + 8) * N + col) = __floats2half2_rn(a4[2], a4[3]);
            } else {
                float v0 = a4[0], v1 = a4[1], v2 = a4[2], v3 = a4[3];
                float2 ra = *(const float2*)(R + (size_t)row * N + col);
                float2 rb = *(const float2*)(R + (size_t)(row + 8) * N + col);
                v0 += ra.x; v1 += ra.y; v2 += rb.x; v3 += rb.y;
                *(float2*)(Cf + (size_t)row * N + col) = make_float2(v0, v1);
                *(float2*)(Cf + (size_t)(row + 8) * N + col) = make_float2(v2, v3);
            }
        }
    }
}

// ========== flash attention via mma.sync (fp16 in/out, fp32 accum) ==========
#define FP2 72   /* padded row: 64 + 8 halves */

__global__ void __launch_bounds__(128) flash_mma(
    const __half* __restrict__ QKV, __half* __restrict__ O)
{
    __shared__ __half Qs[64][FP2];
    __shared__ __half Ks[2][64][FP2];
    __shared__ __half Vs[2][64][FP2];

    const int tid = threadIdx.x;
    const int lane = tid & 31;
    const int wid = tid >> 5;
    const int qi = (int)(gridDim.x - 1 - blockIdx.x);   // longest first
    const int bh = blockIdx.y;
    const int b = bh >> 4, h = bh & 15;
    const size_t qrow0 = (size_t)(b * SEQ + qi * 64);
    const __half* Qg = QKV + qrow0 * QKV_LD + h * DK;
    const __half* Kg = QKV + (size_t)(b * SEQ) * QKV_LD + D_MODEL + h * DK;
    const __half* Vg = QKV + (size_t)(b * SEQ) * QKV_LD + 2 * D_MODEL + h * DK;

    const uint32_t qs_b = smem_to_u32(&Qs[0][0]);
    const uint32_t ks_b = smem_to_u32(&Ks[0][0][0]);
    const uint32_t vs_b = smem_to_u32(&Vs[0][0][0]);
    const uint32_t kv_stage = 64 * FP2 * 2;

    // load Q tile: 64 rows x 8 segs = 512 transfers
    #pragma unroll
    for (int i = 0; i < 4; i++) {
        int idx = tid + i * 128;
        int r = idx >> 3, s = idx & 7;
        cp_async16(qs_b + (uint32_t)(r * FP2 + s * 8) * 2, Qg + (size_t)r * QKV_LD + s * 8);
    }
    CP_COMMIT();
    #pragma unroll
    for (int i = 0; i < 4; i++) {
        int idx = tid + i * 128;
        int r = idx >> 3, s = idx & 7;
        size_t go = (size_t)r * QKV_LD + s * 8;
        cp_async16(ks_b + (uint32_t)(r * FP2 + s * 8) * 2, Kg + go);
        cp_async16(vs_b + (uint32_t)(r * FP2 + s * 8) * 2, Vg + go);
    }
    CP_COMMIT();
    CP_WAIT(1);
    __syncthreads();

    uint32_t qf[4][4];
    #pragma unroll
    for (int ks = 0; ks < 4; ks++) {
        uint32_t addr = qs_b +
            (uint32_t)((wid * 16 + (lane & 15)) * FP2 + ks * 16 + (lane >> 4) * 8) * 2;
        ldsm_x4(qf[ks][0], qf[ks][1], qf[ks][2], qf[ks][3], addr);
    }

    float o[8][4];
    #pragma unroll
    for (int j = 0; j < 8; j++)
        #pragma unroll
        for (int r = 0; r < 4; r++) o[j][r] = 0.f;
    float m0 = -1e30f, m1 = -1e30f, l0 = 0.f, l1 = 0.f;
    const float scale = 0.125f;

    for (int kt = 0; kt <= qi; ++kt) {
        const int st = kt & 1;
        __syncthreads();
        if (kt < qi) {
            const uint32_t so = (uint32_t)(st ^ 1) * kv_stage;
            #pragma unroll
            for (int i = 0; i < 4; i++) {
                int idx = tid + i * 128;
                int r = idx >> 3, s = idx & 7;
                size_t go = (size_t)((kt + 1) * 64 + r) * QKV_LD + s * 8;
                cp_async16(ks_b + so + (uint32_t)(r * FP2 + s * 8) * 2, Kg + go);
                cp_async16(vs_b + so + (uint32_t)(r * FP2 + s * 8) * 2, Vg + go);
            }
            CP_COMMIT();
            CP_WAIT(1);
        } else {
            CP_WAIT(0);
        }
        __syncthreads();

        // ---- S = Q K^T ----
        float sf[8][4];
        #pragma unroll
        for (int j = 0; j < 8; j++)
            #pragma unroll
            for (int r = 0; r < 4; r++) sf[j][r] = 0.f;

        const uint32_t ks_st = ks_b + (uint32_t)st * kv_stage;
        #pragma unroll
        for (int ks = 0; ks < 4; ks++) {
            #pragma unroll
            for (int nb = 0; nb < 4; nb++) {
                uint32_t r0, r1, r2, r3;
                uint32_t addr = ks_st +
                    (uint32_t)((nb * 16 + (lane & 15)) * FP2 + ks * 16 + (lane >> 4) * 8) * 2;
                ldsm_x4(r0, r1, r2, r3, addr);
                mma16816(sf[nb * 2 + 0], qf[ks], r0, r2);
                mma16816(sf[nb * 2 + 1], qf[ks], r1, r3);
            }
        }

        // ---- scale + causal mask ----
        if (kt == qi) {
            const int rg0 = wid * 16 + (lane >> 2);
            #pragma unroll
            for (int j = 0; j < 8; j++) {
                const int c0 = j * 8 + (lane & 3) * 2;
                sf[j][0] = (c0     > rg0    ) ? -1e30f : sf[j][0] * scale;
                sf[j][1] = (c0 + 1 > rg0    ) ? -1e30f : sf[j][1] * scale;
                sf[j][2] = (c0     > rg0 + 8) ? -1e30f : sf[j][2] * scale;
                sf[j][3] = (c0 + 1 > rg0 + 8) ? -1e30f : sf[j][3] * scale;
            }
        } else {
            #pragma unroll
            for (int j = 0; j < 8; j++) {
                sf[j][0] *= scale; sf[j][1] *= scale;
                sf[j][2] *= scale; sf[j][3] *= scale;
            }
        }

        // ---- online softmax ----
        float t0 = -1e30f, t1 = -1e30f;
        #pragma unroll
        for (int j = 0; j < 8; j++) {
            t0 = fmaxf(t0, fmaxf(sf[j][0], sf[j][1]));
            t1 = fmaxf(t1, fmaxf(sf[j][2], sf[j][3]));
        }
        t0 = fmaxf(t0, __shfl_xor_sync(0xffffffffu, t0, 1));
        t0 = fmaxf(t0, __shfl_xor_sync(0xffffffffu, t0, 2));
        t1 = fmaxf(t1, __shfl_xor_sync(0xffffffffu, t1, 1));
        t1 = fmaxf(t1, __shfl_xor_sync(0xffffffffu, t1, 2));

        const float mn0 = fmaxf(m0, t0), mn1 = fmaxf(m1, t1);
        const float a0 = __expf(m0 - mn0), a1 = __expf(m1 - mn1);
        float ps0 = 0.f, ps1 = 0.f;
        #pragma unroll
        for (int j = 0; j < 8; j++) {
            sf[j][0] = __expf(sf[j][0] - mn0);
            sf[j][1] = __expf(sf[j][1] - mn0);
            sf[j][2] = __expf(sf[j][2] - mn1);
            sf[j][3] = __expf(sf[j][3] - mn1);
            ps0 += sf[j][0] + sf[j][1];
            ps1 += sf[j][2] + sf[j][3];
        }
        ps0 += __shfl_xor_sync(0xffffffffu, ps0, 1);
        ps0 += __shfl_xor_sync(0xffffffffu, ps0, 2);
        ps1 += __shfl_xor_sync(0xffffffffu, ps1, 1);
        ps1 += __shfl_xor_sync(0xffffffffu, ps1, 2);
        l0 = l0 * a0 + ps0; l1 = l1 * a1 + ps1;
        m0 = mn0; m1 = mn1;
        #pragma unroll
        for (int j = 0; j < 8; j++) {
            o[j][0] *= a0; o[j][1] *= a0;
            o[j][2] *= a1; o[j][3] *= a1;
        }

        // ---- P -> fp16 A-fragments ----
        uint32_t pf[4][4];
        #pragma unroll
        for (int kk = 0; kk < 4; kk++) {
            pf[kk][0] = packh2(sf[2*kk][0],   sf[2*kk][1]);
            pf[kk][1] = packh2(sf[2*kk][2],   sf[2*kk][3]);
            pf[kk][2] = packh2(sf[2*kk+1][0], sf[2*kk+1][1]);
            pf[kk][3] = packh2(sf[2*kk+1][2], sf[2*kk+1][3]);
        }

        // ---- O += P V ----
        const uint32_t vs_st = vs_b + (uint32_t)st * kv_stage;
        #pragma unroll
        for (int kk = 0; kk < 4; kk++) {
            #pragma unroll
            for (int ns = 0; ns < 4; ns++) {
                uint32_t v0, v1, v2, v3;
                uint32_t addr = vs_st +
                    (uint32_t)((kk * 16 + (lane & 7) + 8 * ((lane >> 3) & 1)) * FP2 +
                               ns * 16 + 8 * (lane >> 4)) * 2;
                ldsm_x4_t(v0, v1, v2, v3, addr);
                mma16816(o[2 * ns + 0], pf[kk], v0, v1);
                mma16816(o[2 * ns + 1], pf[kk], v2, v3);
            }
        }
    }

    // ---- epilogue ----
    const float i0 = 1.f / l0, i1 = 1.f / l1;
    const size_t gr0 = qrow0 + wid * 16 + (lane >> 2);
    #pragma unroll
    for (int j = 0; j < 8; j++) {
        const int col = h * DK + j * 8 + (lane & 3) * 2;
        *(__half2*)(O + gr0 * D_MODEL + col) =
            __floats2half2_rn(o[j][0] * i0, o[j][1] * i0);
        *(__half2*)(O + (gr0 + 8) * D_MODEL + col) =
            __floats2half2_rn(o[j][2] * i1, o[j][3] * i1);
    }
}

// ================= host =================
extern "C" void kernel_launch(void* const* d_in, const int* in_sizes, int n_in,
                              void* d_out, int out_size)
{
    const float* x  = (const float*)d_in[0];
    const float* wq = (const float*)d_in[1];
    const float* wk = (const float*)d_in[2];
    const float* wv = (const float*)d_in[3];
    const float* wo = (const float*)d_in[4];
    const float* w1 = (const float*)d_in[5];
    const float* w2 = (const float*)d_in[6];
    const float* g1 = (const float*)d_in[7];
    const float* g2 = (const float*)d_in[8];
    float* out = (float*)d_out;

    __half *xnh, *qkvh, *atth, *ffhh, *w3h, *woh, *w1h, *w2h;
    float *x1;
    cudaGetSymbolAddress((void**)&xnh,  g_xnh);
    cudaGetSymbolAddress((void**)&qkvh, g_qkvh);
    cudaGetSymbolAddress((void**)&atth, g_atth);
    cudaGetSymbolAddress((void**)&x1,   g_x1);
    cudaGetSymbolAddress((void**)&ffhh, g_ffhh);
    cudaGetSymbolAddress((void**)&w3h,  g_w3h);
    cudaGetSymbolAddress((void**)&woh,  g_woh);
    cudaGetSymbolAddress((void**)&w1h,  g_w1h);
    cudaGetSymbolAddress((void**)&w2h,  g_w2h);

    cudaFuncSetAttribute(hgemm_mma<1>, cudaFuncAttributeMaxDynamicSharedMemorySize, HG_SMEM);
    cudaFuncSetAttribute(hgemm_mma<2>, cudaFuncAttributeMaxDynamicSharedMemorySize, HG_SMEM);
    cudaFuncSetAttribute(hgemm_mma<3>, cudaFuncAttributeMaxDynamicSharedMemorySize, HG_SMEM);

    // weight conversions (fp32 -> fp16); wq|wk|wv concatenated along N
    const int NW = D_MODEL * D_MODEL;
    f2h_kernel<<<NW / 1024, 256>>>(wq, w3h,          NW);
    f2h_kernel<<<NW / 1024, 256>>>(wk, w3h + NW,     NW);
    f2h_kernel<<<NW / 1024, 256>>>(wv, w3h + 2*NW,   NW);
    f2h_kernel<<<NW / 1024, 256>>>(wo, woh, NW);
    f2h_kernel<<<(DFF * D_MODEL) / 1024, 256>>>(w1, w1h, DFF * D_MODEL);
    f2h_kernel<<<(D_MODEL * DFF) / 1024, 256>>>(w2, w2h, D_MODEL * DFF);

    // 1. xn = rmsnorm(x, g1)
    rmsnorm_h_kernel<<<MTOT, 256>>>(x, g1, xnh);

    // 2. qkv = xn @ [wq|wk|wv]^T   (fused, fp16 out)
    dim3 gqkv(QKV_LD / 128, MTOT / 128);
    hgemm_mma<3><<<gqkv, 128, HG_SMEM>>>(xnh, w3h, nullptr, nullptr, qkvh, MTOT, QKV_LD, D_MODEL);

    // 3. att = causal_attention(q,k,v)
    flash_mma<<<dim3(SEQ / 64, BATCH * NHEAD), 128>>>(qkvh, atth);

    // 4. x1 = x + att @ wo^T
    dim3 gproj(D_MODEL / 128, MTOT / 128);
    hgemm_mma<1><<<gproj, 128, HG_SMEM>>>(atth, woh, x, x1, nullptr, MTOT, D_MODEL, D_MODEL);

    // 5. xn = rmsnorm(x1, g2)
    rmsnorm_h_kernel<<<MTOT, 256>>>(x1, g2, xnh);

    // 6. ffh = gelu(xn @ w1^T)
    dim3 gff1(DFF / 128, MTOT / 128);
    hgemm_mma<2><<<gff1, 128, HG_SMEM>>>(xnh, w1h, nullptr, nullptr, ffhh, MTOT, DFF, D_MODEL);

    // 7. out = x1 + ffh @ w2^T
    hgemm_mma<1><<<gproj, 128, HG_SMEM>>>(ffhh, w2h, x1, out, nullptr, MTOT, D_MODEL, DFF);
}

// round 9
// speedup vs baseline: 6.9082x; 1.1435x over previous
#include <cuda_runtime.h>
#include <cuda_fp16.h>
#include <math.h>
#include <stdint.h>

#define D_MODEL 1024
#define NHEAD   16
#define DK      64
#define DFF     4096
#define BATCH   2
#define SEQ     2048
#define MTOT    (BATCH*SEQ)   /* 4096 */
#define EPS_RMS 1e-5f
#define QKV_LD  (3*D_MODEL)   /* 3072 */

// ================= low-level helpers (baseline PTX ISA) =================
__device__ __forceinline__ uint32_t smem_to_u32(const void* p) {
    uint32_t a;
    asm("{ .reg .u64 t; cvta.to.shared.u64 t, %1; cvt.u32.u64 %0, t; }" : "=r"(a) : "l"(p));
    return a;
}
__device__ __forceinline__ void cp_async16(uint32_t dst, const void* src) {
    asm volatile("cp.async.cg.shared.global [%0], [%1], 16;" :: "r"(dst), "l"(src));
}
#define CP_COMMIT() asm volatile("cp.async.commit_group;" ::: "memory")
#define CP_WAIT(n)  asm volatile("cp.async.wait_group %0;" :: "n"(n) : "memory")

__device__ __forceinline__ void ldsm_x4(uint32_t& r0, uint32_t& r1, uint32_t& r2, uint32_t& r3,
                                        uint32_t addr) {
    asm volatile("ldmatrix.sync.aligned.m8n8.x4.shared.b16 {%0,%1,%2,%3}, [%4];"
        : "=r"(r0), "=r"(r1), "=r"(r2), "=r"(r3) : "r"(addr));
}
__device__ __forceinline__ void ldsm_x4_t(uint32_t& r0, uint32_t& r1, uint32_t& r2, uint32_t& r3,
                                          uint32_t addr) {
    asm volatile("ldmatrix.sync.aligned.m8n8.x4.trans.shared.b16 {%0,%1,%2,%3}, [%4];"
        : "=r"(r0), "=r"(r1), "=r"(r2), "=r"(r3) : "r"(addr));
}
__device__ __forceinline__ void mma16816(float* c, const uint32_t* a, uint32_t b0, uint32_t b1) {
    asm volatile("mma.sync.aligned.m16n8k16.row.col.f32.f16.f16.f32 "
        "{%0,%1,%2,%3}, {%4,%5,%6,%7}, {%8,%9}, {%0,%1,%2,%3};"
        : "+f"(c[0]), "+f"(c[1]), "+f"(c[2]), "+f"(c[3])
        : "r"(a[0]), "r"(a[1]), "r"(a[2]), "r"(a[3]), "r"(b0), "r"(b1));
}
__device__ __forceinline__ uint32_t packh2(float a, float b) {
    __half2 h = __floats2half2_rn(a, b);
    return *(uint32_t*)&h;
}

// ================= scratch buffers =================
__device__ __half g_xnh [MTOT*D_MODEL];
__device__ __half g_qkvh[MTOT*QKV_LD];
__device__ __half g_atth[MTOT*D_MODEL];
__device__ float  g_x1  [MTOT*D_MODEL];
__device__ __half g_ffhh[MTOT*DFF];
__device__ __half g_w3h [3*D_MODEL*D_MODEL];   /* concat(wq, wk, wv) */
__device__ __half g_woh [D_MODEL*D_MODEL];
__device__ __half g_w1h [DFF*D_MODEL];
__device__ __half g_w2h [D_MODEL*DFF];

// ============ single-kernel fp32 -> fp16 conversion of ALL weights ============
// ranges (in elements): [0,NW)wq [NW,2NW)wk [2NW,3NW)wv [3NW,4NW)wo
//                       [4NW,8NW)w1 [8NW,12NW)w2       (NW = 1M)
__global__ void __launch_bounds__(256) f2h_all(
    const float* __restrict__ wq, const float* __restrict__ wk,
    const float* __restrict__ wv, const float* __restrict__ wo,
    const float* __restrict__ w1, const float* __restrict__ w2,
    __half* __restrict__ w3h, __half* __restrict__ woh,
    __half* __restrict__ w1h, __half* __restrict__ w2h)
{
    const long NW = (long)D_MODEL * D_MODEL;
    long i = ((long)blockIdx.x * 256 + threadIdx.x) * 4;
    const float* src; __half* dst; long off;
    if (i < NW)            { src = wq; dst = w3h;           off = i; }
    else if (i < 2*NW)     { src = wk; dst = w3h + NW;      off = i - NW; }
    else if (i < 3*NW)     { src = wv; dst = w3h + 2*NW;    off = i - 2*NW; }
    else if (i < 4*NW)     { src = wo; dst = woh;           off = i - 3*NW; }
    else if (i < 8*NW)     { src = w1; dst = w1h;           off = i - 4*NW; }
    else                   { src = w2; dst = w2h;           off = i - 8*NW; }
    float4 v = *(const float4*)(src + off);
    ((__half2*)(dst + off))[0] = __floats2half2_rn(v.x, v.y);
    ((__half2*)(dst + off))[1] = __floats2half2_rn(v.z, v.w);
}

// ================= RMSNorm -> fp16 =================
__global__ void __launch_bounds__(256) rmsnorm_h_kernel(
    const float* __restrict__ x, const float* __restrict__ g, __half* __restrict__ y)
{
    const int row = blockIdx.x;
    const float4* x4 = (const float4*)(x + (size_t)row * D_MODEL);
    const float4* g4 = (const float4*)g;

    float4 v = x4[threadIdx.x];
    float s = v.x*v.x + v.y*v.y + v.z*v.z + v.w*v.w;

    #pragma unroll
    for (int m = 16; m; m >>= 1) s += __shfl_xor_sync(0xffffffffu, s, m);

    __shared__ float red[8];
    int warp = threadIdx.x >> 5, lane = threadIdx.x & 31;
    if (lane == 0) red[warp] = s;
    __syncthreads();
    if (warp == 0) {
        float t = (lane < 8) ? red[lane] : 0.f;
        t += __shfl_xor_sync(0xffffffffu, t, 4);
        t += __shfl_xor_sync(0xffffffffu, t, 2);
        t += __shfl_xor_sync(0xffffffffu, t, 1);
        if (lane == 0) red[0] = t;
    }
    __syncthreads();

    float rms = rsqrtf(red[0] * (1.0f / D_MODEL) + EPS_RMS);
    float4 gg = g4[threadIdx.x];
    __half2* yo = (__half2*)(y + (size_t)row * D_MODEL + threadIdx.x * 4);
    yo[0] = __floats2half2_rn(v.x * rms * gg.x, v.y * rms * gg.y);
    yo[1] = __floats2half2_rn(v.z * rms * gg.z, v.w * rms * gg.w);
}

// ================= GELU =================
__device__ __forceinline__ float gelu_f(float v) {
    return 0.5f * v * (1.0f + erff(v * 0.70710678118654752f));
}

// ====== HGEMM v3: 128 threads, warp tile 64x64, KCH=64, 2-stage cp.async ======
// C[M,N] = A[M,K] * B[N,K]^T. EPI: 1 = fp32 + residual; 2 = fp16 GELU; 3 = fp16
#define KCH    64
#define SPAD   72                          /* 64 + 8 halves padding */
#define HG_STAGE_B (128 * SPAD * 2)        /* 18432 B per matrix per stage */
#define HG_SMEM    (4 * HG_STAGE_B)        /* 2 stages x (A,B) = 73728 B  */

__device__ __forceinline__ void hg_load(
    const __half* __restrict__ G, int base_row, int K, int k0, int tid, uint32_t s_stage)
{
    #pragma unroll
    for (int i = 0; i < 8; i++) {
        int idx = tid + i * 128;              // 0..1023
        int row = idx >> 3, seg = idx & 7;    // 128 rows x 8 16B-segs
        const __half* src = G + (size_t)(base_row + row) * K + k0 + seg * 8;
        cp_async16(s_stage + (uint32_t)(row * SPAD + seg * 8) * 2, src);
    }
}

template <int EPI>
__global__ void __launch_bounds__(128) hgemm_mma(
    const __half* __restrict__ A, const __half* __restrict__ B,
    const float* __restrict__ R, float* __restrict__ Cf, __half* __restrict__ Ch,
    int M, int N, int K)
{
    extern __shared__ __half hsm[];
    const uint32_t a_base = smem_to_u32(hsm);
    const uint32_t b_base = a_base + 2 * HG_STAGE_B;

    const int tid = threadIdx.x;
    const int lane = tid & 31;
    const int wid = tid >> 5;
    const int wy = wid & 1;        // M offset 64*wy
    const int wx = wid >> 1;       // N offset 64*wx
    const int bm = blockIdx.y * 128;
    const int bn = blockIdx.x * 128;

    const int lrow = lane & 15;
    const int koff = (lane >> 4) * 8;

    float acc[4][8][4];
    #pragma unroll
    for (int i = 0; i < 4; i++)
        #pragma unroll
        for (int j = 0; j < 8; j++)
            #pragma unroll
            for (int r = 0; r < 4; r++) acc[i][j][r] = 0.f;

    const int nch = K / KCH;       // 16 (K=1024) or 64 (K=4096)

    // prologue: chunks 0,1 -> stages 0,1
    hg_load(A, bm, K, 0, tid, a_base);
    hg_load(B, bn, K, 0, tid, b_base);
    CP_COMMIT();
    hg_load(A, bm, K, KCH, tid, a_base + HG_STAGE_B);
    hg_load(B, bn, K, KCH, tid, b_base + HG_STAGE_B);
    CP_COMMIT();

    for (int c = 0; c < nch; ++c) {
        if (c + 1 < nch) { CP_WAIT(1); } else { CP_WAIT(0); }
        __syncthreads();

        const uint32_t a_st = a_base + (uint32_t)(c & 1) * HG_STAGE_B;
        const uint32_t b_st = b_base + (uint32_t)(c & 1) * HG_STAGE_B;

        #pragma unroll
        for (int ks = 0; ks < 4; ++ks) {
            uint32_t af[4][4];
            #pragma unroll
            for (int ma = 0; ma < 4; ++ma) {
                uint32_t addr = a_st +
                    (uint32_t)((wy * 64 + ma * 16 + lrow) * SPAD + ks * 16 + koff) * 2;
                ldsm_x4(af[ma][0], af[ma][1], af[ma][2], af[ma][3], addr);
            }
            uint32_t bf[4][4];
            #pragma unroll
            for (int nb = 0; nb < 4; ++nb) {
                uint32_t addr = b_st +
                    (uint32_t)((wx * 64 + nb * 16 + lrow) * SPAD + ks * 16 + koff) * 2;
                ldsm_x4(bf[nb][0], bf[nb][1], bf[nb][2], bf[nb][3], addr);
            }
            #pragma unroll
            for (int ma = 0; ma < 4; ++ma) {
                #pragma unroll
                for (int na = 0; na < 8; ++na) {
                    const uint32_t b0 = bf[na >> 1][(na & 1)];
                    const uint32_t b1 = bf[na >> 1][(na & 1) + 2];
                    mma16816(acc[ma][na], af[ma], b0, b1);
                }
            }
        }
        __syncthreads();

        if (c + 2 < nch) {
            const uint32_t off = (uint32_t)(c & 1) * HG_STAGE_B;
            hg_load(A, bm, K, (c + 2) * KCH, tid, a_base + off);
            hg_load(B, bn, K, (c + 2) * KCH, tid, b_base + off);
            CP_COMMIT();
        }
    }

    // ---------------- epilogue ----------------
    const int r0 = bm + wy * 64 + (lane >> 2);
    const int c0 = bn + wx * 64 + (lane & 3) * 2;

    #pragma unroll
    for (int ma = 0; ma < 4; ++ma) {
        #pragma unroll
        for (int na = 0; na < 8; ++na) {
            const int row = r0 + ma * 16;
            const int col = c0 + na * 8;
            float* a4 = acc[ma][na];
            if (EPI == 2) {
                *(__half2*)(Ch + (size_t)row * N + col) =
                    __floats2half2_rn(gelu_f(a4[0]), gelu_f(a4[1]));
                *(__half2*)(Ch + (size_t)(row + 8) * N + col) =
                    __floats2half2_rn(gelu_f(a4[2]), gelu_f(a4[3]));
            } else if (EPI == 3) {
                *(__half2*)(Ch + (size_t)row * N + col) = __floats2half2_rn(a4[0], a4[1]);
                *(__half2*)(Ch + (size_t)(row + 8) * N + col) = __floats2half2_rn(a4[2], a4[3]);
            } else {
                float v0 = a4[0], v1 = a4[1], v2 = a4[2], v3 = a4[3];
                float2 ra = *(const float2*)(R + (size_t)row * N + col);
                float2 rb = *(const float2*)(R + (size_t)(row + 8) * N + col);
                v0 += ra.x; v1 += ra.y; v2 += rb.x; v3 += rb.y;
                *(float2*)(Cf + (size_t)row * N + col) = make_float2(v0, v1);
                *(float2*)(Cf + (size_t)(row + 8) * N + col) = make_float2(v2, v3);
            }
        }
    }
}

// ========== flash attention via mma.sync (fp16 in/out, fp32 accum) ==========
#define FP2 72   /* padded row: 64 + 8 halves */

__global__ void __launch_bounds__(128) flash_mma(
    const __half* __restrict__ QKV, __half* __restrict__ O)
{
    __shared__ __half Qs[64][FP2];
    __shared__ __half Ks[2][64][FP2];
    __shared__ __half Vs[2][64][FP2];

    const int tid = threadIdx.x;
    const int lane = tid & 31;
    const int wid = tid >> 5;
    const int qi = (int)(gridDim.x - 1 - blockIdx.x);   // longest first
    const int bh = blockIdx.y;
    const int b = bh >> 4, h = bh & 15;
    const size_t qrow0 = (size_t)(b * SEQ + qi * 64);
    const __half* Qg = QKV + qrow0 * QKV_LD + h * DK;
    const __half* Kg = QKV + (size_t)(b * SEQ) * QKV_LD + D_MODEL + h * DK;
    const __half* Vg = QKV + (size_t)(b * SEQ) * QKV_LD + 2 * D_MODEL + h * DK;

    const uint32_t qs_b = smem_to_u32(&Qs[0][0]);
    const uint32_t ks_b = smem_to_u32(&Ks[0][0][0]);
    const uint32_t vs_b = smem_to_u32(&Vs[0][0][0]);
    const uint32_t kv_stage = 64 * FP2 * 2;

    // load Q tile: 64 rows x 8 segs = 512 transfers
    #pragma unroll
    for (int i = 0; i < 4; i++) {
        int idx = tid + i * 128;
        int r = idx >> 3, s = idx & 7;
        cp_async16(qs_b + (uint32_t)(r * FP2 + s * 8) * 2, Qg + (size_t)r * QKV_LD + s * 8);
    }
    CP_COMMIT();
    #pragma unroll
    for (int i = 0; i < 4; i++) {
        int idx = tid + i * 128;
        int r = idx >> 3, s = idx & 7;
        size_t go = (size_t)r * QKV_LD + s * 8;
        cp_async16(ks_b + (uint32_t)(r * FP2 + s * 8) * 2, Kg + go);
        cp_async16(vs_b + (uint32_t)(r * FP2 + s * 8) * 2, Vg + go);
    }
    CP_COMMIT();
    CP_WAIT(1);
    __syncthreads();

    uint32_t qf[4][4];
    #pragma unroll
    for (int ks = 0; ks < 4; ks++) {
        uint32_t addr = qs_b +
            (uint32_t)((wid * 16 + (lane & 15)) * FP2 + ks * 16 + (lane >> 4) * 8) * 2;
        ldsm_x4(qf[ks][0], qf[ks][1], qf[ks][2], qf[ks][3], addr);
    }

    float o[8][4];
    #pragma unroll
    for (int j = 0; j < 8; j++)
        #pragma unroll
        for (int r = 0; r < 4; r++) o[j][r] = 0.f;
    float m0 = -1e30f, m1 = -1e30f, l0 = 0.f, l1 = 0.f;
    const float scale = 0.125f;

    for (int kt = 0; kt <= qi; ++kt) {
        const int st = kt & 1;
        __syncthreads();
        if (kt < qi) {
            const uint32_t so = (uint32_t)(st ^ 1) * kv_stage;
            #pragma unroll
            for (int i = 0; i < 4; i++) {
                int idx = tid + i * 128;
                int r = idx >> 3, s = idx & 7;
                size_t go = (size_t)((kt + 1) * 64 + r) * QKV_LD + s * 8;
                cp_async16(ks_b + so + (uint32_t)(r * FP2 + s * 8) * 2, Kg + go);
                cp_async16(vs_b + so + (uint32_t)(r * FP2 + s * 8) * 2, Vg + go);
            }
            CP_COMMIT();
            CP_WAIT(1);
        } else {
            CP_WAIT(0);
        }
        __syncthreads();

        // ---- S = Q K^T ----
        float sf[8][4];
        #pragma unroll
        for (int j = 0; j < 8; j++)
            #pragma unroll
            for (int r = 0; r < 4; r++) sf[j][r] = 0.f;

        const uint32_t ks_st = ks_b + (uint32_t)st * kv_stage;
        #pragma unroll
        for (int ks = 0; ks < 4; ks++) {
            #pragma unroll
            for (int nb = 0; nb < 4; nb++) {
                uint32_t r0, r1, r2, r3;
                uint32_t addr = ks_st +
                    (uint32_t)((nb * 16 + (lane & 15)) * FP2 + ks * 16 + (lane >> 4) * 8) * 2;
                ldsm_x4(r0, r1, r2, r3, addr);
                mma16816(sf[nb * 2 + 0], qf[ks], r0, r2);
                mma16816(sf[nb * 2 + 1], qf[ks], r1, r3);
            }
        }

        // ---- scale + causal mask ----
        if (kt == qi) {
            const int rg0 = wid * 16 + (lane >> 2);
            #pragma unroll
            for (int j = 0; j < 8; j++) {
                const int c0 = j * 8 + (lane & 3) * 2;
                sf[j][0] = (c0     > rg0    ) ? -1e30f : sf[j][0] * scale;
                sf[j][1] = (c0 + 1 > rg0    ) ? -1e30f : sf[j][1] * scale;
                sf[j][2] = (c0     > rg0 + 8) ? -1e30f : sf[j][2] * scale;
                sf[j][3] = (c0 + 1 > rg0 + 8) ? -1e30f : sf[j][3] * scale;
            }
        } else {
            #pragma unroll
            for (int j = 0; j < 8; j++) {
                sf[j][0] *= scale; sf[j][1] *= scale;
                sf[j][2] *= scale; sf[j][3] *= scale;
            }
        }

        // ---- online softmax ----
        float t0 = -1e30f, t1 = -1e30f;
        #pragma unroll
        for (int j = 0; j < 8; j++) {
            t0 = fmaxf(t0, fmaxf(sf[j][0], sf[j][1]));
            t1 = fmaxf(t1, fmaxf(sf[j][2], sf[j][3]));
        }
        t0 = fmaxf(t0, __shfl_xor_sync(0xffffffffu, t0, 1));
        t0 = fmaxf(t0, __shfl_xor_sync(0xffffffffu, t0, 2));
        t1 = fmaxf(t1, __shfl_xor_sync(0xffffffffu, t1, 1));
        t1 = fmaxf(t1, __shfl_xor_sync(0xffffffffu, t1, 2));

        const float mn0 = fmaxf(m0, t0), mn1 = fmaxf(m1, t1);
        const float a0 = __expf(m0 - mn0), a1 = __expf(m1 - mn1);
        float ps0 = 0.f, ps1 = 0.f;
        #pragma unroll
        for (int j = 0; j < 8; j++) {
            sf[j][0] = __expf(sf[j][0] - mn0);
            sf[j][1] = __expf(sf[j][1] - mn0);
            sf[j][2] = __expf(sf[j][2] - mn1);
            sf[j][3] = __expf(sf[j][3] - mn1);
            ps0 += sf[j][0] + sf[j][1];
            ps1 += sf[j][2] + sf[j][3];
        }
        ps0 += __shfl_xor_sync(0xffffffffu, ps0, 1);
        ps0 += __shfl_xor_sync(0xffffffffu, ps0, 2);
        ps1 += __shfl_xor_sync(0xffffffffu, ps1, 1);
        ps1 += __shfl_xor_sync(0xffffffffu, ps1, 2);
        l0 = l0 * a0 + ps0; l1 = l1 * a1 + ps1;
        m0 = mn0; m1 = mn1;
        #pragma unroll
        for (int j = 0; j < 8; j++) {
            o[j][0] *= a0; o[j][1] *= a0;
            o[j][2] *= a1; o[j][3] *= a1;
        }

        // ---- P -> fp16 A-fragments ----
        uint32_t pf[4][4];
        #pragma unroll
        for (int kk = 0; kk < 4; kk++) {
            pf[kk][0] = packh2(sf[2*kk][0],   sf[2*kk][1]);
            pf[kk][1] = packh2(sf[2*kk][2],   sf[2*kk][3]);
            pf[kk][2] = packh2(sf[2*kk+1][0], sf[2*kk+1][1]);
            pf[kk][3] = packh2(sf[2*kk+1][2], sf[2*kk+1][3]);
        }

        // ---- O += P V ----
        const uint32_t vs_st = vs_b + (uint32_t)st * kv_stage;
        #pragma unroll
        for (int kk = 0; kk < 4; kk++) {
            #pragma unroll
            for (int ns = 0; ns < 4; ns++) {
                uint32_t v0, v1, v2, v3;
                uint32_t addr = vs_st +
                    (uint32_t)((kk * 16 + (lane & 7) + 8 * ((lane >> 3) & 1)) * FP2 +
                               ns * 16 + 8 * (lane >> 4)) * 2;
                ldsm_x4_t(v0, v1, v2, v3, addr);
                mma16816(o[2 * ns + 0], pf[kk], v0, v1);
                mma16816(o[2 * ns + 1], pf[kk], v2, v3);
            }
        }
    }

    // ---- epilogue ----
    const float i0 = 1.f / l0, i1 = 1.f / l1;
    const size_t gr0 = qrow0 + wid * 16 + (lane >> 2);
    #pragma unroll
    for (int j = 0; j < 8; j++) {
        const int col = h * DK + j * 8 + (lane & 3) * 2;
        *(__half2*)(O + gr0 * D_MODEL + col) =
            __floats2half2_rn(o[j][0] * i0, o[j][1] * i0);
        *(__half2*)(O + (gr0 + 8) * D_MODEL + col) =
            __floats2half2_rn(o[j][2] * i1, o[j][3] * i1);
    }
}

// ================= host =================
extern "C" void kernel_launch(void* const* d_in, const int* in_sizes, int n_in,
                              void* d_out, int out_size)
{
    const float* x  = (const float*)d_in[0];
    const float* wq = (const float*)d_in[1];
    const float* wk = (const float*)d_in[2];
    const float* wv = (const float*)d_in[3];
    const float* wo = (const float*)d_in[4];
    const float* w1 = (const float*)d_in[5];
    const float* w2 = (const float*)d_in[6];
    const float* g1 = (const float*)d_in[7];
    const float* g2 = (const float*)d_in[8];
    float* out = (float*)d_out;

    __half *xnh, *qkvh, *atth, *ffhh, *w3h, *woh, *w1h, *w2h;
    float *x1;
    cudaGetSymbolAddress((void**)&xnh,  g_xnh);
    cudaGetSymbolAddress((void**)&qkvh, g_qkvh);
    cudaGetSymbolAddress((void**)&atth, g_atth);
    cudaGetSymbolAddress((void**)&x1,   g_x1);
    cudaGetSymbolAddress((void**)&ffhh, g_ffhh);
    cudaGetSymbolAddress((void**)&w3h,  g_w3h);
    cudaGetSymbolAddress((void**)&woh,  g_woh);
    cudaGetSymbolAddress((void**)&w1h,  g_w1h);
    cudaGetSymbolAddress((void**)&w2h,  g_w2h);

    cudaFuncSetAttribute(hgemm_mma<1>, cudaFuncAttributeMaxDynamicSharedMemorySize, HG_SMEM);
    cudaFuncSetAttribute(hgemm_mma<2>, cudaFuncAttributeMaxDynamicSharedMemorySize, HG_SMEM);
    cudaFuncSetAttribute(hgemm_mma<3>, cudaFuncAttributeMaxDynamicSharedMemorySize, HG_SMEM);

    // 0. all weight conversions in ONE launch (12M elements, 4 per thread)
    f2h_all<<<(12 * D_MODEL * D_MODEL) / 1024, 256>>>(
        wq, wk, wv, wo, w1, w2, w3h, woh, w1h, w2h);

    // 1. xn = rmsnorm(x, g1)
    rmsnorm_h_kernel<<<MTOT, 256>>>(x, g1, xnh);

    // 2. qkv = xn @ [wq|wk|wv]^T   (fused, fp16 out)
    dim3 gqkv(QKV_LD / 128, MTOT / 128);
    hgemm_mma<3><<<gqkv, 128, HG_SMEM>>>(xnh, w3h, nullptr, nullptr, qkvh, MTOT, QKV_LD, D_MODEL);

    // 3. att = causal_attention(q,k,v)
    flash_mma<<<dim3(SEQ / 64, BATCH * NHEAD), 128>>>(qkvh, atth);

    // 4. x1 = x + att @ wo^T
    dim3 gproj(D_MODEL / 128, MTOT / 128);
    hgemm_mma<1><<<gproj, 128, HG_SMEM>>>(atth, woh, x, x1, nullptr, MTOT, D_MODEL, D_MODEL);

    // 5. xn = rmsnorm(x1, g2)
    rmsnorm_h_kernel<<<MTOT, 256>>>(x1, g2, xnh);

    // 6. ffh = gelu(xn @ w1^T)
    dim3 gff1(DFF / 128, MTOT / 128);
    hgemm_mma<2><<<gff1, 128, HG_SMEM>>>(xnh, w1h, nullptr, nullptr, ffhh, MTOT, DFF, D_MODEL);

    // 7. out = x1 + ffh @ w2^T
    hgemm_mma<1><<<gproj, 128, HG_SMEM>>>(ffhh, w2h, x1, out, nullptr, MTOT, D_MODEL, DFF);
}